// round 9
// baseline (speedup 1.0000x reference)
#include <cuda_runtime.h>
#include <cuda_bf16.h>

#define NN 100000
#define FF 64
#define HH 128
#define CC 10
#define EE 1600000
#define NB 98   // ceil(NN/1024)

typedef unsigned int uint;

// ---------------- scratch ----------------
__device__ uint g_P0h[(size_t)NN * 64], g_P0l[(size_t)NN * 64];
__device__ uint g_P1h[(size_t)NN * 64], g_P1l[(size_t)NN * 64];
__device__ uint g_P2h[(size_t)NN * 64], g_P2l[(size_t)NN * 64];
__device__ float g_h[(size_t)NN * HH];
__device__ uint g_Wh[5 * 8192], g_Wl[5 * 8192];
__device__ int g_deg[NN], g_rowptr[NN + 1], g_cur[NN], g_adj[EE];
__device__ int g_bsum[NB], g_bpre[NB];
__device__ float g_stats[512];   // [0:128) sum [128:256) sumsq [256:384) scale [384:512) shift
__device__ int g_is64;

// ---------------- helpers ----------------
__device__ __forceinline__ uint pckbf(__nv_bfloat16 a, __nv_bfloat16 b) {
    __nv_bfloat162 t; t.x = a; t.y = b;
    return *reinterpret_cast<uint*>(&t);
}
__device__ __forceinline__ void split2(float x, float y, uint& h, uint& l) {
    __nv_bfloat16 hx = __float2bfloat16_rn(x), hy = __float2bfloat16_rn(y);
    float rx = x - __bfloat162float(hx), ry = y - __bfloat162float(hy);
    h = pckbf(hx, hy);
    l = pckbf(__float2bfloat16_rn(rx), __float2bfloat16_rn(ry));
}
__device__ __forceinline__ float2 bf2f(uint u) {
    __nv_bfloat162 b = *reinterpret_cast<__nv_bfloat162*>(&u);
    return make_float2(__bfloat162float(b.x), __bfloat162float(b.y));
}
__device__ __forceinline__ void mma16816(float* d, uint a0, uint a1, uint a2,
                                         uint a3, uint b0, uint b1) {
    asm volatile("mma.sync.aligned.m16n8k16.row.col.f32.bf16.bf16.f32 "
                 "{%0,%1,%2,%3},{%4,%5,%6,%7},{%8,%9},{%0,%1,%2,%3};"
                 : "+f"(d[0]), "+f"(d[1]), "+f"(d[2]), "+f"(d[3])
                 : "r"(a0), "r"(a1), "r"(a2), "r"(a3), "r"(b0), "r"(b1));
}
__device__ __forceinline__ void eidx(const int* ei, int e, int& s, int& d) {
    if (g_is64) { s = ei[2 * e]; d = ei[2 * EE + 2 * e]; }
    else        { s = ei[e];     d = ei[EE + e]; }
}
__device__ __forceinline__ uint smem_u32(const void* p) {
    uint a;
    asm("{ .reg .u64 t; cvta.to.shared.u64 t, %1; cvt.u32.u64 %0, t; }" : "=r"(a) : "l"(p));
    return a;
}
__device__ __forceinline__ void cpa16(uint dst, const void* src, int sz) {
    asm volatile("cp.async.cg.shared.global [%0], [%1], 16, %2;"
                 :: "r"(dst), "l"(src), "r"(sz));
}
#define CPA_COMMIT() asm volatile("cp.async.commit_group;" ::: "memory")
#define CPA_WAIT2()  asm volatile("cp.async.wait_group 2;" ::: "memory")
#define CPA_WAIT1()  asm volatile("cp.async.wait_group 1;" ::: "memory")
#define CPA_WAIT0()  asm volatile("cp.async.wait_group 0;" ::: "memory")

// ---------------- setup: zero deg + dtype detect + weight pre-split (one launch) ----------------
__global__ void k_setup(const int* __restrict__ ei,
                        const float* __restrict__ w1a, const float* __restrict__ w1b,
                        const float* __restrict__ w2a, const float* __restrict__ w2b,
                        const float* __restrict__ mw1) {
    int i = blockIdx.x * blockDim.x + threadIdx.x;
    if (i < NN) g_deg[i] = 0;
    if (i == 0) {
        int nz = 0;
        for (int k = 0; k < 1024; k++) nz |= ei[2 * k + 1];
        g_is64 = (nz == 0) ? 1 : 0;
    }
    if (i < 4096 + 4 * 8192) {
        const float* W;
        int slot, li, RW;
        if (i < 4096) { W = w1a; slot = 0; li = i; RW = 32; }
        else {
            int j = i - 4096;
            int s = j >> 13;
            li = j & 8191;
            RW = 64;
            slot = 1 + s;
            W = (s == 0) ? w1b : (s == 1) ? w2a : (s == 2) ? w2b : mw1;
        }
        int n = li / RW, kp = li - n * RW;
        split2(W[(size_t)(2 * kp) * 128 + n], W[(size_t)(2 * kp + 1) * 128 + n],
               g_Wh[slot * 8192 + li], g_Wl[slot * 8192 + li]);
    }
}

// ---------------- CSR build ----------------
__global__ void k_deg(const int* __restrict__ ei) {
    int e = blockIdx.x * blockDim.x + threadIdx.x;
    if (e >= EE) return;
    int s, d;
    eidx(ei, e, s, d);
    if ((unsigned)s >= NN || (unsigned)d >= NN) return;
    atomicAdd(&g_deg[d], 1);
}
__global__ void k_bsum() {
    __shared__ int sh[1024];
    int t = threadIdx.x;
    int i = blockIdx.x * 1024 + t;
    sh[t] = (i < NN) ? g_deg[i] : 0;
    __syncthreads();
    for (int off = 512; off > 0; off >>= 1) {
        if (t < off) sh[t] += sh[t + off];
        __syncthreads();
    }
    if (t == 0) g_bsum[blockIdx.x] = sh[0];
}
__global__ void k_bscan() {
    __shared__ int sh[128];
    int t = threadIdx.x;
    sh[t] = (t < NB) ? g_bsum[t] : 0;
    __syncthreads();
    for (int off = 1; off < 128; off <<= 1) {
        int v = (t >= off) ? sh[t - off] : 0;
        __syncthreads();
        sh[t] += v;
        __syncthreads();
    }
    if (t < NB) g_bpre[t] = (t == 0) ? 0 : sh[t - 1];
    if (t == NB - 1) g_rowptr[NN] = sh[t];
}
__global__ void k_scan3() {
    __shared__ int sh[1024];
    int t = threadIdx.x;
    int i = blockIdx.x * 1024 + t;
    int d = (i < NN) ? g_deg[i] : 0;
    sh[t] = d;
    __syncthreads();
    for (int off = 1; off < 1024; off <<= 1) {
        int v = (t >= off) ? sh[t - off] : 0;
        __syncthreads();
        sh[t] += v;
        __syncthreads();
    }
    if (i < NN) {
        int r = g_bpre[blockIdx.x] + sh[t] - d;
        g_rowptr[i] = r;
        g_cur[i] = r;
    }
}
__global__ void k_fill(const int* __restrict__ ei) {
    int e = blockIdx.x * blockDim.x + threadIdx.x;
    if (e >= EE) return;
    int s, d;
    eidx(ei, e, s, d);
    if ((unsigned)s >= NN || (unsigned)d >= NN) return;
    int pos = atomicAdd(&g_cur[d], 1);
    g_adj[pos] = s;
}

// ---------------- gather1: agg = x_self + sum x_j, split to pair (width 64) ----------------
__global__ void k_gather1(const float* __restrict__ x, uint* __restrict__ Oh,
                          uint* __restrict__ Ol) {
    int gi = blockIdx.x * blockDim.x + threadIdx.x;
    int node = gi >> 4, l = gi & 15;
    if (node >= NN) return;
    const float4* xr = (const float4*)x;
    float4 acc = xr[(size_t)node * 16 + l];
    int p = g_rowptr[node], end = g_rowptr[node + 1];
    for (; p + 3 < end; p += 4) {
        int j0 = g_adj[p], j1 = g_adj[p + 1], j2 = g_adj[p + 2], j3 = g_adj[p + 3];
        float4 a = xr[(size_t)j0 * 16 + l];
        float4 b = xr[(size_t)j1 * 16 + l];
        float4 cg = xr[(size_t)j2 * 16 + l];
        float4 d = xr[(size_t)j3 * 16 + l];
        acc.x += (a.x + b.x) + (cg.x + d.x);
        acc.y += (a.y + b.y) + (cg.y + d.y);
        acc.z += (a.z + b.z) + (cg.z + d.z);
        acc.w += (a.w + b.w) + (cg.w + d.w);
    }
    for (; p < end; p++) {
        float4 a = xr[(size_t)g_adj[p] * 16 + l];
        acc.x += a.x; acc.y += a.y; acc.z += a.z; acc.w += a.w;
    }
    uint h0, l0, h1, l1;
    split2(acc.x, acc.y, h0, l0);
    split2(acc.z, acc.w, h1, l1);
    size_t o = (size_t)node * 32 + l * 2;
    *(uint2*)(Oh + o) = make_uint2(h0, h1);
    *(uint2*)(Ol + o) = make_uint2(l0, l1);
}

// ---------------- gather2: agg = sum_{self+nbrs} relu(bn(v)), pair width 128 ----------------
__global__ void k_gather2(const uint* __restrict__ Ih, const uint* __restrict__ Il,
                          uint* __restrict__ Oh, uint* __restrict__ Ol) {
    int node = blockIdx.x * 4 + (threadIdx.x >> 5);
    int l = threadIdx.x & 31;
    if (node >= NN) return;
    float4 sc = *(const float4*)&g_stats[256 + l * 4];
    float4 sh = *(const float4*)&g_stats[384 + l * 4];
    float a0 = 0.f, a1 = 0.f, a2 = 0.f, a3 = 0.f;
#define ADDROW(j) do { \
        size_t _o = (size_t)(j) * 64 + l * 2; \
        uint2 uh = *(const uint2*)(Ih + _o); \
        uint2 ul = *(const uint2*)(Il + _o); \
        float2 fa = bf2f(uh.x), fb = bf2f(ul.x), fc = bf2f(uh.y), fd = bf2f(ul.y); \
        a0 += fmaxf(fmaf(fa.x + fb.x, sc.x, sh.x), 0.f); \
        a1 += fmaxf(fmaf(fa.y + fb.y, sc.y, sh.y), 0.f); \
        a2 += fmaxf(fmaf(fc.x + fd.x, sc.z, sh.z), 0.f); \
        a3 += fmaxf(fmaf(fc.y + fd.y, sc.w, sh.w), 0.f); \
    } while (0)
    ADDROW(node);
    int p = g_rowptr[node], end = g_rowptr[node + 1];
    for (; p + 3 < end; p += 4) {
        int j0 = g_adj[p], j1 = g_adj[p + 1], j2 = g_adj[p + 2], j3 = g_adj[p + 3];
        ADDROW(j0);
        ADDROW(j1);
        ADDROW(j2);
        ADDROW(j3);
    }
    for (; p < end; p++) ADDROW(g_adj[p]);
#undef ADDROW
    uint h0, l0, h1, l1;
    split2(a0, a1, h0, l0);
    split2(a2, a3, h1, l1);
    size_t o = (size_t)node * 64 + l * 2;
    *(uint2*)(Oh + o) = make_uint2(h0, h1);
    *(uint2*)(Ol + o) = make_uint2(l0, l1);
}

// ---------------- 3-stage cp.async bf16-split3 GEMM ----------------
// OUTMODE: 0 = fp32 out, 1 = pair out, 2 = pair out + BN stats atomics
// Per stage (words): Ah @0, Al @1536, Bh @3072, Bl @4608; stage stride 6144, 3 stages.
template <int K, bool RELU, int OUTMODE>
__global__ void __launch_bounds__(256, 2)
k_mgemm(const uint* __restrict__ Ah, const uint* __restrict__ Al,
        const uint* __restrict__ Wh, const uint* __restrict__ Wl,
        const float* __restrict__ bias,
        float* __restrict__ OutF, uint* __restrict__ Oh, uint* __restrict__ Ol) {
    extern __shared__ uint smd[];
    __shared__ float sbias[128];

    const int tid = threadIdx.x;
    const int wid = tid >> 5, lane = tid & 31;
    const int wm = wid >> 1, wn = wid & 1;
    const int g = lane >> 2, t = lane & 3;
    const int row0 = blockIdx.x * 128;
    const int RW = K / 2;
    const int CHK = K / 16;

    const int r = tid >> 1, half = tid & 1;
    const uint sb = smem_u32(smd);
    const int rr = min(row0 + r, NN - 1);
    const int okA = (row0 + r < NN) ? 16 : 0;

    if (tid < 128) sbias[tid] = bias[tid];

#define PREFETCH(c, st) do { \
        uint _d = sb + (uint)((st) * 6144 + r * 12 + half * 4) * 4u; \
        size_t _ao = (size_t)rr * RW + (c) * 8 + half * 4; \
        size_t _wo = (size_t)r * RW + (c) * 8 + half * 4; \
        cpa16(_d,         Ah + _ao, okA); \
        cpa16(_d + 6144,  Al + _ao, okA); \
        cpa16(_d + 12288, Wh + _wo, 16); \
        cpa16(_d + 18432, Wl + _wo, 16); \
        CPA_COMMIT(); \
    } while (0)

    float acc[2][8][4];
    #pragma unroll
    for (int i = 0; i < 2; i++)
        #pragma unroll
        for (int j = 0; j < 8; j++)
            #pragma unroll
            for (int q = 0; q < 4; q++) acc[i][j][q] = 0.f;

    PREFETCH(0, 0);
    if (CHK > 1) PREFETCH(1, 1);

    int buf = 0, nxt = (CHK > 1) ? 2 : 1;   // nxt = stage slot for chunk c+2
    for (int c = 0; c < CHK; c++) {
        if (c + 2 < CHK) {
            PREFETCH(c + 2, nxt);
            if (++nxt == 3) nxt = 0;
            CPA_WAIT2();
        } else if (c + 1 < CHK) {
            CPA_WAIT1();
        } else {
            CPA_WAIT0();
        }
        __syncthreads();
        const uint* S = smd + buf * 6144;
        if (++buf == 3) buf = 0;
        const uint* Sal = S + 1536;
        const uint* Sbh = S + 3072;
        const uint* Sbl = S + 4608;

        uint bh[8][2], bl[8][2];
        #pragma unroll
        for (int nt = 0; nt < 8; nt++) {
            int n = wn * 64 + nt * 8 + g;
            bh[nt][0] = Sbh[n * 12 + t]; bh[nt][1] = Sbh[n * 12 + t + 4];
            bl[nt][0] = Sbl[n * 12 + t]; bl[nt][1] = Sbl[n * 12 + t + 4];
        }
        #pragma unroll
        for (int mt = 0; mt < 2; mt++) {
            int rb = wm * 32 + mt * 16;
            uint ah0 = S[(rb + g) * 12 + t],       ah1 = S[(rb + 8 + g) * 12 + t];
            uint ah2 = S[(rb + g) * 12 + t + 4],   ah3 = S[(rb + 8 + g) * 12 + t + 4];
            uint al0 = Sal[(rb + g) * 12 + t],     al1 = Sal[(rb + 8 + g) * 12 + t];
            uint al2 = Sal[(rb + g) * 12 + t + 4], al3 = Sal[(rb + 8 + g) * 12 + t + 4];
            #pragma unroll
            for (int nt = 0; nt < 8; nt++) {
                mma16816(acc[mt][nt], ah0, ah1, ah2, ah3, bh[nt][0], bh[nt][1]);
                mma16816(acc[mt][nt], ah0, ah1, ah2, ah3, bl[nt][0], bl[nt][1]);
                mma16816(acc[mt][nt], al0, al1, al2, al3, bh[nt][0], bh[nt][1]);
            }
        }
        __syncthreads();
    }
#undef PREFETCH

    // ---- epilogue: bias (+relu), stores, optional fused BN column stats
    #pragma unroll
    for (int nt = 0; nt < 8; nt++) {
        int cc = wn * 64 + nt * 8 + 2 * t;
        float b0 = sbias[cc], b1 = sbias[cc + 1];
        float s0 = 0.f, q0 = 0.f, s1 = 0.f, q1 = 0.f;
        #pragma unroll
        for (int mt = 0; mt < 2; mt++) {
            int r0r = row0 + wm * 32 + mt * 16 + g;
            float d0 = acc[mt][nt][0] + b0, d1 = acc[mt][nt][1] + b1;
            float d2 = acc[mt][nt][2] + b0, d3 = acc[mt][nt][3] + b1;
            if (RELU) {
                d0 = fmaxf(d0, 0.f); d1 = fmaxf(d1, 0.f);
                d2 = fmaxf(d2, 0.f); d3 = fmaxf(d3, 0.f);
            }
            if (OUTMODE >= 1) {
                uint h, l;
                if (r0r < NN) {
                    split2(d0, d1, h, l);
                    Oh[(size_t)r0r * 64 + (cc >> 1)] = h;
                    Ol[(size_t)r0r * 64 + (cc >> 1)] = l;
                }
                if (r0r + 8 < NN) {
                    split2(d2, d3, h, l);
                    Oh[(size_t)(r0r + 8) * 64 + (cc >> 1)] = h;
                    Ol[(size_t)(r0r + 8) * 64 + (cc >> 1)] = l;
                }
            } else {
                if (r0r < NN) *(float2*)(OutF + (size_t)r0r * 128 + cc) = make_float2(d0, d1);
                if (r0r + 8 < NN) *(float2*)(OutF + (size_t)(r0r + 8) * 128 + cc) = make_float2(d2, d3);
            }
            if (OUTMODE == 2) {
                if (r0r < NN) {
                    s0 += d0; q0 = fmaf(d0, d0, q0);
                    s1 += d1; q1 = fmaf(d1, d1, q1);
                }
                if (r0r + 8 < NN) {
                    s0 += d2; q0 = fmaf(d2, d2, q0);
                    s1 += d3; q1 = fmaf(d3, d3, q1);
                }
            }
        }
        if (OUTMODE == 2) {
            #pragma unroll
            for (int off = 4; off < 32; off <<= 1) {
                s0 += __shfl_xor_sync(0xffffffffu, s0, off);
                q0 += __shfl_xor_sync(0xffffffffu, q0, off);
                s1 += __shfl_xor_sync(0xffffffffu, s1, off);
                q1 += __shfl_xor_sync(0xffffffffu, q1, off);
            }
            if (lane < 4) {
                atomicAdd(&g_stats[cc], s0);
                atomicAdd(&g_stats[128 + cc], q0);
                atomicAdd(&g_stats[cc + 1], s1);
                atomicAdd(&g_stats[128 + cc + 1], q1);
            }
        }
    }
}

// ---------------- BN finalize (self-cleans the accumulators for next use) ----------------
__global__ void k_bnfin(const float* __restrict__ g, const float* __restrict__ b) {
    int c = threadIdx.x;
    float inv = 1.f / (float)NN;
    float mean = g_stats[c] * inv;
    float var = g_stats[128 + c] * inv - mean * mean;
    float rstd = rsqrtf(var + 1e-5f);
    float sc = g[c] * rstd;
    g_stats[256 + c] = sc;
    g_stats[384 + c] = b[c] - mean * sc;
    g_stats[c] = 0.f;
    g_stats[128 + c] = 0.f;
}

// bnapply2: pair in -> fp32 latent (d_out) + pair out (classifier input)
__global__ void k_bnapply2(const uint* __restrict__ Ih, const uint* __restrict__ Il,
                           float* __restrict__ OutF, uint* __restrict__ Oh,
                           uint* __restrict__ Ol) {
    int i = blockIdx.x * blockDim.x + threadIdx.x;
    if (i >= NN * 64) return;
    int c = (i & 63) * 2;
    float2 fh = bf2f(Ih[i]);
    float2 fl = bf2f(Il[i]);
    float v0 = fh.x + fl.x, v1 = fh.y + fl.y;
    float y0 = fmaxf(fmaf(v0, g_stats[256 + c], g_stats[384 + c]), 0.f);
    float y1 = fmaxf(fmaf(v1, g_stats[257 + c], g_stats[385 + c]), 0.f);
    int r = i >> 6;
    *(float2*)(OutF + (size_t)r * 128 + c) = make_float2(y0, y1);
    uint h, l;
    split2(y0, y1, h, l);
    Oh[i] = h;
    Ol[i] = l;
}

// ---------------- classifier head: out[N,10] = m[N,128] @ w[128,10] + b ----------------
__global__ void __launch_bounds__(128) k_out(const float* __restrict__ m,
                                             const float* __restrict__ w,
                                             const float* __restrict__ b,
                                             float* __restrict__ out) {
    __shared__ float Wsm[1280];
    __shared__ float Ms[128][33];
    int tid = threadIdx.x;
    for (int i = tid; i < 1280; i += 128) Wsm[i] = w[i];
    long long row0 = (long long)blockIdx.x * 128;
    float acc[10];
    #pragma unroll
    for (int c = 0; c < 10; c++) acc[c] = b[c];
    for (int k0 = 0; k0 < 128; k0 += 32) {
        __syncthreads();
        for (int i = tid; i < 1024; i += 128) {
            int r = i >> 3, c4 = i & 7;
            long long gr = row0 + r;
            float4 v = make_float4(0.f, 0.f, 0.f, 0.f);
            if (gr < NN) v = *(const float4*)(m + gr * 128 + k0 + c4 * 4);
            Ms[r][c4 * 4] = v.x; Ms[r][c4 * 4 + 1] = v.y;
            Ms[r][c4 * 4 + 2] = v.z; Ms[r][c4 * 4 + 3] = v.w;
        }
        __syncthreads();
        #pragma unroll
        for (int kk = 0; kk < 32; kk++) {
            float a = Ms[tid][kk];
            #pragma unroll
            for (int c = 0; c < 10; c++) acc[c] = fmaf(a, Wsm[(k0 + kk) * 10 + c], acc[c]);
        }
    }
    long long gr = row0 + tid;
    if (gr < NN) {
        #pragma unroll
        for (int c = 0; c < 10; c++) out[gr * 10 + c] = acc[c];
    }
}

// ---------------- launch ----------------
extern "C" void kernel_launch(void* const* d_in, const int* in_sizes, int n_in,
                              void* d_out, int out_size) {
    const float* x    = (const float*)d_in[0];
    const int*   ei   = (const int*)d_in[1];
    const float* w1a = (const float*)d_in[2];  const float* b1a = (const float*)d_in[3];
    const float* w1b = (const float*)d_in[4];  const float* b1b = (const float*)d_in[5];
    const float* w2a = (const float*)d_in[6];  const float* b2a = (const float*)d_in[7];
    const float* w2b = (const float*)d_in[8];  const float* b2b = (const float*)d_in[9];
    const float* bn1g = (const float*)d_in[10]; const float* bn1b = (const float*)d_in[11];
    const float* bn2g = (const float*)d_in[12]; const float* bn2b = (const float*)d_in[13];
    const float* mw1 = (const float*)d_in[14]; const float* mb1 = (const float*)d_in[15];
    const float* mw2 = (const float*)d_in[16]; const float* mb2 = (const float*)d_in[17];
    float* out = (float*)d_out;

    uint *P0h, *P0l, *P1h, *P1l, *P2h, *P2l, *Wh, *Wl;
    float* hh;
    cudaGetSymbolAddress((void**)&P0h, g_P0h); cudaGetSymbolAddress((void**)&P0l, g_P0l);
    cudaGetSymbolAddress((void**)&P1h, g_P1h); cudaGetSymbolAddress((void**)&P1l, g_P1l);
    cudaGetSymbolAddress((void**)&P2h, g_P2h); cudaGetSymbolAddress((void**)&P2l, g_P2l);
    cudaGetSymbolAddress((void**)&Wh, g_Wh);   cudaGetSymbolAddress((void**)&Wl, g_Wl);
    cudaGetSymbolAddress((void**)&hh, g_h);

    const int GB = (NN + 127) / 128;  // 782
    const int EB = (EE + 255) / 256;
    const int SMEM_G = 3 * 6144 * 4;  // 73728 B dynamic (3-stage)

    cudaFuncSetAttribute(k_mgemm<64, true, 1>,   cudaFuncAttributeMaxDynamicSharedMemorySize, SMEM_G);
    cudaFuncSetAttribute(k_mgemm<128, false, 2>, cudaFuncAttributeMaxDynamicSharedMemorySize, SMEM_G);
    cudaFuncSetAttribute(k_mgemm<128, true, 1>,  cudaFuncAttributeMaxDynamicSharedMemorySize, SMEM_G);
    cudaFuncSetAttribute(k_mgemm<128, true, 0>,  cudaFuncAttributeMaxDynamicSharedMemorySize, SMEM_G);

    // ---- setup + CSR build
    k_setup<<<(NN + 255) / 256, 256>>>(ei, w1a, w1b, w2a, w2b, mw1);
    k_deg<<<EB, 256>>>(ei);
    k_bsum<<<NB, 1024>>>();
    k_bscan<<<1, 128>>>();
    k_scan3<<<NB, 1024>>>();
    k_fill<<<EB, 256>>>(ei);

    // ---- conv1
    k_gather1<<<(NN * 16 + 127) / 128, 128>>>(x, P0h, P0l);
    k_mgemm<64, true, 1><<<GB, 256, SMEM_G>>>(P0h, P0l, Wh, Wl, b1a, 0, P1h, P1l);
    k_mgemm<128, false, 2><<<GB, 256, SMEM_G>>>(P1h, P1l, Wh + 8192, Wl + 8192, b1b, 0, P2h, P2l);
    k_bnfin<<<1, 128>>>(bn1g, bn1b);
    // ---- conv2 (gather applies relu(bn(.)) per term)
    k_gather2<<<(NN + 3) / 4, 128>>>(P2h, P2l, P0h, P0l);
    k_mgemm<128, true, 1><<<GB, 256, SMEM_G>>>(P0h, P0l, Wh + 2 * 8192, Wl + 2 * 8192, b2a, 0, P1h, P1l);
    k_mgemm<128, false, 2><<<GB, 256, SMEM_G>>>(P1h, P1l, Wh + 3 * 8192, Wl + 3 * 8192, b2b, 0, P2h, P2l);
    k_bnfin<<<1, 128>>>(bn2g, bn2b);
    k_bnapply2<<<(NN * 64 + 255) / 256, 256>>>(P2h, P2l, out, P0h, P0l);
    // ---- classifier
    k_mgemm<128, true, 0><<<GB, 256, SMEM_G>>>(P0h, P0l, Wh + 4 * 8192, Wl + 4 * 8192, mb1, hh, 0, 0);
    k_out<<<GB, 128>>>(hh, mw2, mb2, out + (size_t)NN * 128);
}

// round 10
// speedup vs baseline: 1.0816x; 1.0816x over previous
#include <cuda_runtime.h>
#include <cuda_bf16.h>

#define NN 100000
#define FF 64
#define HH 128
#define CC 10
#define EE 1600000
#define NB 98   // ceil(NN/1024)

typedef unsigned int uint;

// ---------------- scratch ----------------
__device__ uint g_P0h[(size_t)NN * 64], g_P0l[(size_t)NN * 64];
__device__ uint g_P1h[(size_t)NN * 64], g_P1l[(size_t)NN * 64];
__device__ uint g_P2h[(size_t)NN * 64], g_P2l[(size_t)NN * 64];
__device__ float g_h[(size_t)NN * HH];
__device__ uint g_Wh[5 * 8192], g_Wl[5 * 8192];
__device__ int g_deg[NN], g_rowptr[NN + 1], g_cur[NN], g_adj[EE];
__device__ int g_bsum[NB], g_bpre[NB];
__device__ float g_stats[512];   // [0:128) sum [128:256) sumsq [256:384) scale [384:512) shift
__device__ int g_is64;

// ---------------- helpers ----------------
__device__ __forceinline__ uint pckbf(__nv_bfloat16 a, __nv_bfloat16 b) {
    __nv_bfloat162 t; t.x = a; t.y = b;
    return *reinterpret_cast<uint*>(&t);
}
__device__ __forceinline__ void split2(float x, float y, uint& h, uint& l) {
    __nv_bfloat16 hx = __float2bfloat16_rn(x), hy = __float2bfloat16_rn(y);
    float rx = x - __bfloat162float(hx), ry = y - __bfloat162float(hy);
    h = pckbf(hx, hy);
    l = pckbf(__float2bfloat16_rn(rx), __float2bfloat16_rn(ry));
}
__device__ __forceinline__ float2 bf2f(uint u) {
    __nv_bfloat162 b = *reinterpret_cast<__nv_bfloat162*>(&u);
    return make_float2(__bfloat162float(b.x), __bfloat162float(b.y));
}
__device__ __forceinline__ void mma16816(float* d, uint a0, uint a1, uint a2,
                                         uint a3, uint b0, uint b1) {
    asm volatile("mma.sync.aligned.m16n8k16.row.col.f32.bf16.bf16.f32 "
                 "{%0,%1,%2,%3},{%4,%5,%6,%7},{%8,%9},{%0,%1,%2,%3};"
                 : "+f"(d[0]), "+f"(d[1]), "+f"(d[2]), "+f"(d[3])
                 : "r"(a0), "r"(a1), "r"(a2), "r"(a3), "r"(b0), "r"(b1));
}
__device__ __forceinline__ void eidx(const int* ei, int e, int& s, int& d) {
    if (g_is64) { s = ei[2 * e]; d = ei[2 * EE + 2 * e]; }
    else        { s = ei[e];     d = ei[EE + e]; }
}
__device__ __forceinline__ uint smem_u32(const void* p) {
    uint a;
    asm("{ .reg .u64 t; cvta.to.shared.u64 t, %1; cvt.u32.u64 %0, t; }" : "=r"(a) : "l"(p));
    return a;
}
__device__ __forceinline__ void cpa16(uint dst, const void* src, int sz) {
    asm volatile("cp.async.cg.shared.global [%0], [%1], 16, %2;"
                 :: "r"(dst), "l"(src), "r"(sz));
}
#define CPA_COMMIT() asm volatile("cp.async.commit_group;" ::: "memory")
#define CPA_WAIT1()  asm volatile("cp.async.wait_group 1;" ::: "memory")
#define CPA_WAIT0()  asm volatile("cp.async.wait_group 0;" ::: "memory")

// ---------------- setup: zero deg + dtype detect + weight pre-split (one launch) ----------------
__global__ void k_setup(const int* __restrict__ ei,
                        const float* __restrict__ w1a, const float* __restrict__ w1b,
                        const float* __restrict__ w2a, const float* __restrict__ w2b,
                        const float* __restrict__ mw1) {
    int i = blockIdx.x * blockDim.x + threadIdx.x;
    if (i < NN) g_deg[i] = 0;
    if (i == 0) {
        int nz = 0;
        for (int k = 0; k < 1024; k++) nz |= ei[2 * k + 1];
        g_is64 = (nz == 0) ? 1 : 0;
    }
    if (i < 4096 + 4 * 8192) {
        const float* W;
        int slot, li, RW;
        if (i < 4096) { W = w1a; slot = 0; li = i; RW = 32; }
        else {
            int j = i - 4096;
            int s = j >> 13;
            li = j & 8191;
            RW = 64;
            slot = 1 + s;
            W = (s == 0) ? w1b : (s == 1) ? w2a : (s == 2) ? w2b : mw1;
        }
        int n = li / RW, kp = li - n * RW;
        split2(W[(size_t)(2 * kp) * 128 + n], W[(size_t)(2 * kp + 1) * 128 + n],
               g_Wh[slot * 8192 + li], g_Wl[slot * 8192 + li]);
    }
}

// ---------------- CSR build ----------------
__global__ void k_deg(const int* __restrict__ ei) {
    int e = blockIdx.x * blockDim.x + threadIdx.x;
    if (e >= EE) return;
    int s, d;
    eidx(ei, e, s, d);
    if ((unsigned)s >= NN || (unsigned)d >= NN) return;
    atomicAdd(&g_deg[d], 1);
}
__global__ void k_bsum() {
    __shared__ int sh[1024];
    int t = threadIdx.x;
    int i = blockIdx.x * 1024 + t;
    sh[t] = (i < NN) ? g_deg[i] : 0;
    __syncthreads();
    for (int off = 512; off > 0; off >>= 1) {
        if (t < off) sh[t] += sh[t + off];
        __syncthreads();
    }
    if (t == 0) g_bsum[blockIdx.x] = sh[0];
}
__global__ void k_bscan() {
    __shared__ int sh[128];
    int t = threadIdx.x;
    sh[t] = (t < NB) ? g_bsum[t] : 0;
    __syncthreads();
    for (int off = 1; off < 128; off <<= 1) {
        int v = (t >= off) ? sh[t - off] : 0;
        __syncthreads();
        sh[t] += v;
        __syncthreads();
    }
    if (t < NB) g_bpre[t] = (t == 0) ? 0 : sh[t - 1];
    if (t == NB - 1) g_rowptr[NN] = sh[t];
}
__global__ void k_scan3() {
    __shared__ int sh[1024];
    int t = threadIdx.x;
    int i = blockIdx.x * 1024 + t;
    int d = (i < NN) ? g_deg[i] : 0;
    sh[t] = d;
    __syncthreads();
    for (int off = 1; off < 1024; off <<= 1) {
        int v = (t >= off) ? sh[t - off] : 0;
        __syncthreads();
        sh[t] += v;
        __syncthreads();
    }
    if (i < NN) {
        int r = g_bpre[blockIdx.x] + sh[t] - d;
        g_rowptr[i] = r;
        g_cur[i] = r;
    }
}
__global__ void k_fill(const int* __restrict__ ei) {
    int e = blockIdx.x * blockDim.x + threadIdx.x;
    if (e >= EE) return;
    int s, d;
    eidx(ei, e, s, d);
    if ((unsigned)s >= NN || (unsigned)d >= NN) return;
    int pos = atomicAdd(&g_cur[d], 1);
    g_adj[pos] = s;
}

// ---------------- gather1: agg = x_self + sum x_j, split to pair (width 64) ----------------
__global__ void k_gather1(const float* __restrict__ x, uint* __restrict__ Oh,
                          uint* __restrict__ Ol) {
    int gi = blockIdx.x * blockDim.x + threadIdx.x;
    int node = gi >> 4, l = gi & 15;
    if (node >= NN) return;
    const float4* xr = (const float4*)x;
    float4 acc = xr[(size_t)node * 16 + l];
    int p = g_rowptr[node], end = g_rowptr[node + 1];
    for (; p + 1 < end; p += 2) {
        int j0 = g_adj[p], j1 = g_adj[p + 1];
        float4 a = xr[(size_t)j0 * 16 + l];
        float4 b = xr[(size_t)j1 * 16 + l];
        acc.x += a.x + b.x; acc.y += a.y + b.y;
        acc.z += a.z + b.z; acc.w += a.w + b.w;
    }
    if (p < end) {
        float4 a = xr[(size_t)g_adj[p] * 16 + l];
        acc.x += a.x; acc.y += a.y; acc.z += a.z; acc.w += a.w;
    }
    uint h0, l0, h1, l1;
    split2(acc.x, acc.y, h0, l0);
    split2(acc.z, acc.w, h1, l1);
    size_t o = (size_t)node * 32 + l * 2;
    *(uint2*)(Oh + o) = make_uint2(h0, h1);
    *(uint2*)(Ol + o) = make_uint2(l0, l1);
}

// ---------------- gather2: agg = sum_{self+nbrs} relu(bn(v)), pair width 128 ----------------
__global__ void k_gather2(const uint* __restrict__ Ih, const uint* __restrict__ Il,
                          uint* __restrict__ Oh, uint* __restrict__ Ol) {
    int node = blockIdx.x * 4 + (threadIdx.x >> 5);
    int l = threadIdx.x & 31;
    if (node >= NN) return;
    float4 sc = *(const float4*)&g_stats[256 + l * 4];
    float4 sh = *(const float4*)&g_stats[384 + l * 4];
    float a0 = 0.f, a1 = 0.f, a2 = 0.f, a3 = 0.f;
#define ADDROW(j) do { \
        size_t _o = (size_t)(j) * 64 + l * 2; \
        uint2 uh = *(const uint2*)(Ih + _o); \
        uint2 ul = *(const uint2*)(Il + _o); \
        float2 fa = bf2f(uh.x), fb = bf2f(ul.x), fc = bf2f(uh.y), fd = bf2f(ul.y); \
        a0 += fmaxf(fmaf(fa.x + fb.x, sc.x, sh.x), 0.f); \
        a1 += fmaxf(fmaf(fa.y + fb.y, sc.y, sh.y), 0.f); \
        a2 += fmaxf(fmaf(fc.x + fd.x, sc.z, sh.z), 0.f); \
        a3 += fmaxf(fmaf(fc.y + fd.y, sc.w, sh.w), 0.f); \
    } while (0)
    ADDROW(node);
    int p = g_rowptr[node], end = g_rowptr[node + 1];
    for (; p + 1 < end; p += 2) {
        int j0 = g_adj[p], j1 = g_adj[p + 1];
        ADDROW(j0);
        ADDROW(j1);
    }
    if (p < end) ADDROW(g_adj[p]);
#undef ADDROW
    uint h0, l0, h1, l1;
    split2(a0, a1, h0, l0);
    split2(a2, a3, h1, l1);
    size_t o = (size_t)node * 64 + l * 2;
    *(uint2*)(Oh + o) = make_uint2(h0, h1);
    *(uint2*)(Ol + o) = make_uint2(l0, l1);
}

// ---------------- double-buffered cp.async bf16-split3 GEMM (R7-proven config) ----------------
// OUTMODE: 0 = fp32 out, 1 = pair out, 2 = pair out + BN stats atomics
// smem stage layout (words): Ah @0, Al @1536, Bh @3072, Bl @4608; stage stride 6144.
template <int K, bool RELU, int OUTMODE>
__global__ void __launch_bounds__(256, 2)
k_mgemm(const uint* __restrict__ Ah, const uint* __restrict__ Al,
        const uint* __restrict__ Wh, const uint* __restrict__ Wl,
        const float* __restrict__ bias,
        float* __restrict__ OutF, uint* __restrict__ Oh, uint* __restrict__ Ol) {
    extern __shared__ uint smd[];
    __shared__ float sbias[128];

    const int tid = threadIdx.x;
    const int wid = tid >> 5, lane = tid & 31;
    const int wm = wid >> 1, wn = wid & 1;
    const int g = lane >> 2, t = lane & 3;
    const int row0 = blockIdx.x * 128;
    const int RW = K / 2;
    const int CHK = K / 16;

    const int r = tid >> 1, half = tid & 1;
    const uint sb = smem_u32(smd);
    const int rr = min(row0 + r, NN - 1);
    const int okA = (row0 + r < NN) ? 16 : 0;

    if (tid < 128) sbias[tid] = bias[tid];

#define PREFETCH(c, st) do { \
        uint _d = sb + (uint)((st) * 6144 + r * 12 + half * 4) * 4u; \
        size_t _ao = (size_t)rr * RW + (c) * 8 + half * 4; \
        size_t _wo = (size_t)r * RW + (c) * 8 + half * 4; \
        cpa16(_d,         Ah + _ao, okA); \
        cpa16(_d + 6144,  Al + _ao, okA); \
        cpa16(_d + 12288, Wh + _wo, 16); \
        cpa16(_d + 18432, Wl + _wo, 16); \
        CPA_COMMIT(); \
    } while (0)

    float acc[2][8][4];
    #pragma unroll
    for (int i = 0; i < 2; i++)
        #pragma unroll
        for (int j = 0; j < 8; j++)
            #pragma unroll
            for (int q = 0; q < 4; q++) acc[i][j][q] = 0.f;

    PREFETCH(0, 0);

    for (int c = 0; c < CHK; c++) {
        if (c + 1 < CHK) {
            PREFETCH(c + 1, (c + 1) & 1);
            CPA_WAIT1();
        } else {
            CPA_WAIT0();
        }
        __syncthreads();
        const uint* S = smd + (c & 1) * 6144;
        const uint* Sal = S + 1536;
        const uint* Sbh = S + 3072;
        const uint* Sbl = S + 4608;

        uint bh[8][2], bl[8][2];
        #pragma unroll
        for (int nt = 0; nt < 8; nt++) {
            int n = wn * 64 + nt * 8 + g;
            bh[nt][0] = Sbh[n * 12 + t]; bh[nt][1] = Sbh[n * 12 + t + 4];
            bl[nt][0] = Sbl[n * 12 + t]; bl[nt][1] = Sbl[n * 12 + t + 4];
        }
        #pragma unroll
        for (int mt = 0; mt < 2; mt++) {
            int rb = wm * 32 + mt * 16;
            uint ah0 = S[(rb + g) * 12 + t],       ah1 = S[(rb + 8 + g) * 12 + t];
            uint ah2 = S[(rb + g) * 12 + t + 4],   ah3 = S[(rb + 8 + g) * 12 + t + 4];
            uint al0 = Sal[(rb + g) * 12 + t],     al1 = Sal[(rb + 8 + g) * 12 + t];
            uint al2 = Sal[(rb + g) * 12 + t + 4], al3 = Sal[(rb + 8 + g) * 12 + t + 4];
            #pragma unroll
            for (int nt = 0; nt < 8; nt++) {
                mma16816(acc[mt][nt], ah0, ah1, ah2, ah3, bh[nt][0], bh[nt][1]);
                mma16816(acc[mt][nt], ah0, ah1, ah2, ah3, bl[nt][0], bl[nt][1]);
                mma16816(acc[mt][nt], al0, al1, al2, al3, bh[nt][0], bh[nt][1]);
            }
        }
        __syncthreads();
    }
#undef PREFETCH

    // ---- epilogue: bias (+relu), stores, optional fused BN column stats
    #pragma unroll
    for (int nt = 0; nt < 8; nt++) {
        int cc = wn * 64 + nt * 8 + 2 * t;
        float b0 = sbias[cc], b1 = sbias[cc + 1];
        float s0 = 0.f, q0 = 0.f, s1 = 0.f, q1 = 0.f;
        #pragma unroll
        for (int mt = 0; mt < 2; mt++) {
            int r0r = row0 + wm * 32 + mt * 16 + g;
            float d0 = acc[mt][nt][0] + b0, d1 = acc[mt][nt][1] + b1;
            float d2 = acc[mt][nt][2] + b0, d3 = acc[mt][nt][3] + b1;
            if (RELU) {
                d0 = fmaxf(d0, 0.f); d1 = fmaxf(d1, 0.f);
                d2 = fmaxf(d2, 0.f); d3 = fmaxf(d3, 0.f);
            }
            if (OUTMODE >= 1) {
                uint h, l;
                if (r0r < NN) {
                    split2(d0, d1, h, l);
                    Oh[(size_t)r0r * 64 + (cc >> 1)] = h;
                    Ol[(size_t)r0r * 64 + (cc >> 1)] = l;
                }
                if (r0r + 8 < NN) {
                    split2(d2, d3, h, l);
                    Oh[(size_t)(r0r + 8) * 64 + (cc >> 1)] = h;
                    Ol[(size_t)(r0r + 8) * 64 + (cc >> 1)] = l;
                }
            } else {
                if (r0r < NN) *(float2*)(OutF + (size_t)r0r * 128 + cc) = make_float2(d0, d1);
                if (r0r + 8 < NN) *(float2*)(OutF + (size_t)(r0r + 8) * 128 + cc) = make_float2(d2, d3);
            }
            if (OUTMODE == 2) {
                if (r0r < NN) {
                    s0 += d0; q0 = fmaf(d0, d0, q0);
                    s1 += d1; q1 = fmaf(d1, d1, q1);
                }
                if (r0r + 8 < NN) {
                    s0 += d2; q0 = fmaf(d2, d2, q0);
                    s1 += d3; q1 = fmaf(d3, d3, q1);
                }
            }
        }
        if (OUTMODE == 2) {
            #pragma unroll
            for (int off = 4; off < 32; off <<= 1) {
                s0 += __shfl_xor_sync(0xffffffffu, s0, off);
                q0 += __shfl_xor_sync(0xffffffffu, q0, off);
                s1 += __shfl_xor_sync(0xffffffffu, s1, off);
                q1 += __shfl_xor_sync(0xffffffffu, q1, off);
            }
            if (lane < 4) {
                atomicAdd(&g_stats[cc], s0);
                atomicAdd(&g_stats[128 + cc], q0);
                atomicAdd(&g_stats[cc + 1], s1);
                atomicAdd(&g_stats[128 + cc + 1], q1);
            }
        }
    }
}

// ---------------- BN finalize (self-cleans the accumulators for next use) ----------------
__global__ void k_bnfin(const float* __restrict__ g, const float* __restrict__ b) {
    int c = threadIdx.x;
    float inv = 1.f / (float)NN;
    float mean = g_stats[c] * inv;
    float var = g_stats[128 + c] * inv - mean * mean;
    float rstd = rsqrtf(var + 1e-5f);
    float sc = g[c] * rstd;
    g_stats[256 + c] = sc;
    g_stats[384 + c] = b[c] - mean * sc;
    g_stats[c] = 0.f;
    g_stats[128 + c] = 0.f;
}

// bnapply2: pair in -> fp32 latent (d_out) + pair out (classifier input)
__global__ void k_bnapply2(const uint* __restrict__ Ih, const uint* __restrict__ Il,
                           float* __restrict__ OutF, uint* __restrict__ Oh,
                           uint* __restrict__ Ol) {
    int i = blockIdx.x * blockDim.x + threadIdx.x;
    if (i >= NN * 64) return;
    int c = (i & 63) * 2;
    float2 fh = bf2f(Ih[i]);
    float2 fl = bf2f(Il[i]);
    float v0 = fh.x + fl.x, v1 = fh.y + fl.y;
    float y0 = fmaxf(fmaf(v0, g_stats[256 + c], g_stats[384 + c]), 0.f);
    float y1 = fmaxf(fmaf(v1, g_stats[257 + c], g_stats[385 + c]), 0.f);
    int r = i >> 6;
    *(float2*)(OutF + (size_t)r * 128 + c) = make_float2(y0, y1);
    uint h, l;
    split2(y0, y1, h, l);
    Oh[i] = h;
    Ol[i] = l;
}

// ---------------- classifier head: out[N,10] = m[N,128] @ w[128,10] + b ----------------
__global__ void __launch_bounds__(128) k_out(const float* __restrict__ m,
                                             const float* __restrict__ w,
                                             const float* __restrict__ b,
                                             float* __restrict__ out) {
    __shared__ float Wsm[1280];
    __shared__ float Ms[128][33];
    int tid = threadIdx.x;
    for (int i = tid; i < 1280; i += 128) Wsm[i] = w[i];
    long long row0 = (long long)blockIdx.x * 128;
    float acc[10];
    #pragma unroll
    for (int c = 0; c < 10; c++) acc[c] = b[c];
    for (int k0 = 0; k0 < 128; k0 += 32) {
        __syncthreads();
        for (int i = tid; i < 1024; i += 128) {
            int r = i >> 3, c4 = i & 7;
            long long gr = row0 + r;
            float4 v = make_float4(0.f, 0.f, 0.f, 0.f);
            if (gr < NN) v = *(const float4*)(m + gr * 128 + k0 + c4 * 4);
            Ms[r][c4 * 4] = v.x; Ms[r][c4 * 4 + 1] = v.y;
            Ms[r][c4 * 4 + 2] = v.z; Ms[r][c4 * 4 + 3] = v.w;
        }
        __syncthreads();
        #pragma unroll
        for (int kk = 0; kk < 32; kk++) {
            float a = Ms[tid][kk];
            #pragma unroll
            for (int c = 0; c < 10; c++) acc[c] = fmaf(a, Wsm[(k0 + kk) * 10 + c], acc[c]);
        }
    }
    long long gr = row0 + tid;
    if (gr < NN) {
        #pragma unroll
        for (int c = 0; c < 10; c++) out[gr * 10 + c] = acc[c];
    }
}

// ---------------- launch ----------------
extern "C" void kernel_launch(void* const* d_in, const int* in_sizes, int n_in,
                              void* d_out, int out_size) {
    const float* x    = (const float*)d_in[0];
    const int*   ei   = (const int*)d_in[1];
    const float* w1a = (const float*)d_in[2];  const float* b1a = (const float*)d_in[3];
    const float* w1b = (const float*)d_in[4];  const float* b1b = (const float*)d_in[5];
    const float* w2a = (const float*)d_in[6];  const float* b2a = (const float*)d_in[7];
    const float* w2b = (const float*)d_in[8];  const float* b2b = (const float*)d_in[9];
    const float* bn1g = (const float*)d_in[10]; const float* bn1b = (const float*)d_in[11];
    const float* bn2g = (const float*)d_in[12]; const float* bn2b = (const float*)d_in[13];
    const float* mw1 = (const float*)d_in[14]; const float* mb1 = (const float*)d_in[15];
    const float* mw2 = (const float*)d_in[16]; const float* mb2 = (const float*)d_in[17];
    float* out = (float*)d_out;

    uint *P0h, *P0l, *P1h, *P1l, *P2h, *P2l, *Wh, *Wl;
    float* hh;
    cudaGetSymbolAddress((void**)&P0h, g_P0h); cudaGetSymbolAddress((void**)&P0l, g_P0l);
    cudaGetSymbolAddress((void**)&P1h, g_P1h); cudaGetSymbolAddress((void**)&P1l, g_P1l);
    cudaGetSymbolAddress((void**)&P2h, g_P2h); cudaGetSymbolAddress((void**)&P2l, g_P2l);
    cudaGetSymbolAddress((void**)&Wh, g_Wh);   cudaGetSymbolAddress((void**)&Wl, g_Wl);
    cudaGetSymbolAddress((void**)&hh, g_h);

    const int GB = (NN + 127) / 128;  // 782
    const int EB = (EE + 255) / 256;
    const int SMEM_G = 2 * 6144 * 4;  // 49152 B dynamic (2-stage, R7-proven)

    cudaFuncSetAttribute(k_mgemm<64, true, 1>,   cudaFuncAttributeMaxDynamicSharedMemorySize, SMEM_G);
    cudaFuncSetAttribute(k_mgemm<128, false, 2>, cudaFuncAttributeMaxDynamicSharedMemorySize, SMEM_G);
    cudaFuncSetAttribute(k_mgemm<128, true, 1>,  cudaFuncAttributeMaxDynamicSharedMemorySize, SMEM_G);
    cudaFuncSetAttribute(k_mgemm<128, true, 0>,  cudaFuncAttributeMaxDynamicSharedMemorySize, SMEM_G);

    // ---- setup + CSR build
    k_setup<<<(NN + 255) / 256, 256>>>(ei, w1a, w1b, w2a, w2b, mw1);
    k_deg<<<EB, 256>>>(ei);
    k_bsum<<<NB, 1024>>>();
    k_bscan<<<1, 128>>>();
    k_scan3<<<NB, 1024>>>();
    k_fill<<<EB, 256>>>(ei);

    // ---- conv1
    k_gather1<<<(NN * 16 + 127) / 128, 128>>>(x, P0h, P0l);
    k_mgemm<64, true, 1><<<GB, 256, SMEM_G>>>(P0h, P0l, Wh, Wl, b1a, 0, P1h, P1l);
    k_mgemm<128, false, 2><<<GB, 256, SMEM_G>>>(P1h, P1l, Wh + 8192, Wl + 8192, b1b, 0, P2h, P2l);
    k_bnfin<<<1, 128>>>(bn1g, bn1b);
    // ---- conv2 (gather applies relu(bn(.)) per term)
    k_gather2<<<(NN + 3) / 4, 128>>>(P2h, P2l, P0h, P0l);
    k_mgemm<128, true, 1><<<GB, 256, SMEM_G>>>(P0h, P0l, Wh + 2 * 8192, Wl + 2 * 8192, b2a, 0, P1h, P1l);
    k_mgemm<128, false, 2><<<GB, 256, SMEM_G>>>(P1h, P1l, Wh + 3 * 8192, Wl + 3 * 8192, b2b, 0, P2h, P2l);
    k_bnfin<<<1, 128>>>(bn2g, bn2b);
    k_bnapply2<<<(NN * 64 + 255) / 256, 256>>>(P2h, P2l, out, P0h, P0l);
    // ---- classifier
    k_mgemm<128, true, 0><<<GB, 256, SMEM_G>>>(P0h, P0l, Wh + 4 * 8192, Wl + 4 * 8192, mb1, hh, 0, 0);
    k_out<<<GB, 128>>>(hh, mw2, mb2, out + (size_t)NN * 128);
}

// round 11
// speedup vs baseline: 1.1075x; 1.0239x over previous
#include <cuda_runtime.h>
#include <cuda_bf16.h>

#define NN 100000
#define FF 64
#define HH 128
#define CC 10
#define EE 1600000
#define NB 98   // ceil(NN/1024)

typedef unsigned int uint;

// ---------------- scratch ----------------
__device__ uint g_P0h[(size_t)NN * 64], g_P0l[(size_t)NN * 64];
__device__ uint g_P1h[(size_t)NN * 64], g_P1l[(size_t)NN * 64];
__device__ uint g_P2h[(size_t)NN * 64], g_P2l[(size_t)NN * 64];
__device__ uint g_Wh[5 * 8192], g_Wl[5 * 8192];
__device__ int g_deg[NN], g_rowptr[NN + 1], g_cur[NN], g_adj[EE];
__device__ int g_bsum[NB], g_bpre[NB];
__device__ float g_stats[512];   // [0:128) sum [128:256) sumsq [256:384) scale [384:512) shift
__device__ int g_is64;
__device__ int g_cnt, g_flag;

// ---------------- helpers ----------------
__device__ __forceinline__ uint pckbf(__nv_bfloat16 a, __nv_bfloat16 b) {
    __nv_bfloat162 t; t.x = a; t.y = b;
    return *reinterpret_cast<uint*>(&t);
}
__device__ __forceinline__ void split2(float x, float y, uint& h, uint& l) {
    __nv_bfloat16 hx = __float2bfloat16_rn(x), hy = __float2bfloat16_rn(y);
    float rx = x - __bfloat162float(hx), ry = y - __bfloat162float(hy);
    h = pckbf(hx, hy);
    l = pckbf(__float2bfloat16_rn(rx), __float2bfloat16_rn(ry));
}
__device__ __forceinline__ float2 bf2f(uint u) {
    __nv_bfloat162 b = *reinterpret_cast<__nv_bfloat162*>(&u);
    return make_float2(__bfloat162float(b.x), __bfloat162float(b.y));
}
__device__ __forceinline__ void mma16816(float* d, uint a0, uint a1, uint a2,
                                         uint a3, uint b0, uint b1) {
    asm volatile("mma.sync.aligned.m16n8k16.row.col.f32.bf16.bf16.f32 "
                 "{%0,%1,%2,%3},{%4,%5,%6,%7},{%8,%9},{%0,%1,%2,%3};"
                 : "+f"(d[0]), "+f"(d[1]), "+f"(d[2]), "+f"(d[3])
                 : "r"(a0), "r"(a1), "r"(a2), "r"(a3), "r"(b0), "r"(b1));
}
__device__ __forceinline__ void eidx(const int* ei, int e, int& s, int& d) {
    if (g_is64) { s = ei[2 * e]; d = ei[2 * EE + 2 * e]; }
    else        { s = ei[e];     d = ei[EE + e]; }
}
__device__ __forceinline__ uint smem_u32(const void* p) {
    uint a;
    asm("{ .reg .u64 t; cvta.to.shared.u64 t, %1; cvt.u32.u64 %0, t; }" : "=r"(a) : "l"(p));
    return a;
}
__device__ __forceinline__ void cpa16(uint dst, const void* src, int sz) {
    asm volatile("cp.async.cg.shared.global [%0], [%1], 16, %2;"
                 :: "r"(dst), "l"(src), "r"(sz));
}
#define CPA_COMMIT() asm volatile("cp.async.commit_group;" ::: "memory")
#define CPA_WAIT1()  asm volatile("cp.async.wait_group 1;" ::: "memory")
#define CPA_WAIT0()  asm volatile("cp.async.wait_group 0;" ::: "memory")

// ---------------- setup: zero deg + sync flags + dtype detect + weight pre-split ----------------
__global__ void k_setup(const int* __restrict__ ei,
                        const float* __restrict__ w1a, const float* __restrict__ w1b,
                        const float* __restrict__ w2a, const float* __restrict__ w2b,
                        const float* __restrict__ mw1) {
    int i = blockIdx.x * blockDim.x + threadIdx.x;
    if (i < NN) g_deg[i] = 0;
    if (i == 0) {
        int nz = 0;
        for (int k = 0; k < 1024; k++) nz |= ei[2 * k + 1];
        g_is64 = (nz == 0) ? 1 : 0;
        g_cnt = 0;
        g_flag = 0;
    }
    if (i < 4096 + 4 * 8192) {
        const float* W;
        int slot, li, RW;
        if (i < 4096) { W = w1a; slot = 0; li = i; RW = 32; }
        else {
            int j = i - 4096;
            int s = j >> 13;
            li = j & 8191;
            RW = 64;
            slot = 1 + s;
            W = (s == 0) ? w1b : (s == 1) ? w2a : (s == 2) ? w2b : mw1;
        }
        int n = li / RW, kp = li - n * RW;
        split2(W[(size_t)(2 * kp) * 128 + n], W[(size_t)(2 * kp + 1) * 128 + n],
               g_Wh[slot * 8192 + li], g_Wl[slot * 8192 + li]);
    }
}

// ---------------- CSR build ----------------
__global__ void k_deg(const int* __restrict__ ei) {
    int e = blockIdx.x * blockDim.x + threadIdx.x;
    if (e >= EE) return;
    int s, d;
    eidx(ei, e, s, d);
    if ((unsigned)s >= NN || (unsigned)d >= NN) return;
    atomicAdd(&g_deg[d], 1);
}

// single-kernel scan: per-chunk scan + global sync via counter/flag (all 98 blocks resident)
__global__ void __launch_bounds__(1024) k_scan_all() {
    __shared__ int sh[1024];
    __shared__ int s2[128];
    __shared__ int lastf;
    int t = threadIdx.x, b = blockIdx.x;
    int i = b * 1024 + t;
    int d = (i < NN) ? g_deg[i] : 0;
    sh[t] = d;
    __syncthreads();
    for (int off = 1; off < 1024; off <<= 1) {
        int v = (t >= off) ? sh[t - off] : 0;
        __syncthreads();
        sh[t] += v;
        __syncthreads();
    }
    if (t == 1023) {
        g_bsum[b] = sh[1023];
        __threadfence();
        lastf = (atomicAdd(&g_cnt, 1) == NB - 1);
    }
    __syncthreads();
    if (lastf) {
        if (t < 128) s2[t] = (t < NB) ? ((volatile int*)g_bsum)[t] : 0;
        __syncthreads();
        for (int off = 1; off < 128; off <<= 1) {
            int v = (t < 128 && t >= off) ? s2[t - off] : 0;
            __syncthreads();
            if (t < 128) s2[t] += v;
            __syncthreads();
        }
        if (t < NB) g_bpre[t] = (t == 0) ? 0 : s2[t - 1];
        if (t == NB - 1) g_rowptr[NN] = s2[t];
        __threadfence();
        __syncthreads();
        if (t == 0) atomicExch(&g_flag, 1);
    }
    if (t == 0) {
        while (atomicAdd(&g_flag, 0) == 0) { }
    }
    __syncthreads();
    if (i < NN) {
        int r = ((volatile int*)g_bpre)[b] + sh[t] - d;
        g_rowptr[i] = r;
        g_cur[i] = r;
    }
}

__global__ void k_fill(const int* __restrict__ ei) {
    int e = blockIdx.x * blockDim.x + threadIdx.x;
    if (e >= EE) return;
    int s, d;
    eidx(ei, e, s, d);
    if ((unsigned)s >= NN || (unsigned)d >= NN) return;
    int pos = atomicAdd(&g_cur[d], 1);
    g_adj[pos] = s;
}

// ---------------- gather1: agg = x_self + sum x_j, split to pair (width 64) ----------------
__global__ void k_gather1(const float* __restrict__ x, uint* __restrict__ Oh,
                          uint* __restrict__ Ol) {
    int gi = blockIdx.x * blockDim.x + threadIdx.x;
    int node = gi >> 4, l = gi & 15;
    if (node >= NN) return;
    const float4* xr = (const float4*)x;
    float4 acc = xr[(size_t)node * 16 + l];
    int p = g_rowptr[node], end = g_rowptr[node + 1];
    for (; p + 1 < end; p += 2) {
        int j0 = g_adj[p], j1 = g_adj[p + 1];
        float4 a = xr[(size_t)j0 * 16 + l];
        float4 b = xr[(size_t)j1 * 16 + l];
        acc.x += a.x + b.x; acc.y += a.y + b.y;
        acc.z += a.z + b.z; acc.w += a.w + b.w;
    }
    if (p < end) {
        float4 a = xr[(size_t)g_adj[p] * 16 + l];
        acc.x += a.x; acc.y += a.y; acc.z += a.z; acc.w += a.w;
    }
    uint h0, l0, h1, l1;
    split2(acc.x, acc.y, h0, l0);
    split2(acc.z, acc.w, h1, l1);
    size_t o = (size_t)node * 32 + l * 2;
    *(uint2*)(Oh + o) = make_uint2(h0, h1);
    *(uint2*)(Ol + o) = make_uint2(l0, l1);
}

// ---------------- gather2: agg = sum_{self+nbrs} relu(bn(v)), pair width 128 ----------------
__global__ void k_gather2(const uint* __restrict__ Ih, const uint* __restrict__ Il,
                          uint* __restrict__ Oh, uint* __restrict__ Ol) {
    int node = blockIdx.x * 4 + (threadIdx.x >> 5);
    int l = threadIdx.x & 31;
    if (node >= NN) return;
    float4 sc = *(const float4*)&g_stats[256 + l * 4];
    float4 sh = *(const float4*)&g_stats[384 + l * 4];
    float a0 = 0.f, a1 = 0.f, a2 = 0.f, a3 = 0.f;
#define ADDROW(j) do { \
        size_t _o = (size_t)(j) * 64 + l * 2; \
        uint2 uh = *(const uint2*)(Ih + _o); \
        uint2 ul = *(const uint2*)(Il + _o); \
        float2 fa = bf2f(uh.x), fb = bf2f(ul.x), fc = bf2f(uh.y), fd = bf2f(ul.y); \
        a0 += fmaxf(fmaf(fa.x + fb.x, sc.x, sh.x), 0.f); \
        a1 += fmaxf(fmaf(fa.y + fb.y, sc.y, sh.y), 0.f); \
        a2 += fmaxf(fmaf(fc.x + fd.x, sc.z, sh.z), 0.f); \
        a3 += fmaxf(fmaf(fc.y + fd.y, sc.w, sh.w), 0.f); \
    } while (0)
    ADDROW(node);
    int p = g_rowptr[node], end = g_rowptr[node + 1];
    for (; p + 1 < end; p += 2) {
        int j0 = g_adj[p], j1 = g_adj[p + 1];
        ADDROW(j0);
        ADDROW(j1);
    }
    if (p < end) ADDROW(g_adj[p]);
#undef ADDROW
    uint h0, l0, h1, l1;
    split2(a0, a1, h0, l0);
    split2(a2, a3, h1, l1);
    size_t o = (size_t)node * 64 + l * 2;
    *(uint2*)(Oh + o) = make_uint2(h0, h1);
    *(uint2*)(Ol + o) = make_uint2(l0, l1);
}

// ---------------- double-buffered cp.async bf16-split3 GEMM ----------------
// OUTMODE: 1 = pair out, 2 = pair out + BN stats atomics, 3 = fused classifier head
// smem stage layout (words): Ah @0, Al @1536, Bh @3072, Bl @4608; stage stride 6144.
// Mode 3 reuses smem after mainloop: m-tile [128][132] @0, W2 @16896, b2 @18176.
template <int K, bool RELU, int OUTMODE>
__global__ void __launch_bounds__(256, 2)
k_mgemm(const uint* __restrict__ Ah, const uint* __restrict__ Al,
        const uint* __restrict__ Wh, const uint* __restrict__ Wl,
        const float* __restrict__ bias,
        float* __restrict__ OutF, uint* __restrict__ Oh, uint* __restrict__ Ol,
        const float* __restrict__ W2, const float* __restrict__ B2) {
    extern __shared__ uint smd[];
    __shared__ float sbias[128];

    const int tid = threadIdx.x;
    const int wid = tid >> 5, lane = tid & 31;
    const int wm = wid >> 1, wn = wid & 1;
    const int g = lane >> 2, t = lane & 3;
    const int row0 = blockIdx.x * 128;
    const int RW = K / 2;
    const int CHK = K / 16;

    const int r = tid >> 1, half = tid & 1;
    const uint sb = smem_u32(smd);
    const int rr = min(row0 + r, NN - 1);
    const int okA = (row0 + r < NN) ? 16 : 0;

    if (tid < 128) sbias[tid] = bias[tid];

#define PREFETCH(c, st) do { \
        uint _d = sb + (uint)((st) * 6144 + r * 12 + half * 4) * 4u; \
        size_t _ao = (size_t)rr * RW + (c) * 8 + half * 4; \
        size_t _wo = (size_t)r * RW + (c) * 8 + half * 4; \
        cpa16(_d,         Ah + _ao, okA); \
        cpa16(_d + 6144,  Al + _ao, okA); \
        cpa16(_d + 12288, Wh + _wo, 16); \
        cpa16(_d + 18432, Wl + _wo, 16); \
        CPA_COMMIT(); \
    } while (0)

    float acc[2][8][4];
    #pragma unroll
    for (int i = 0; i < 2; i++)
        #pragma unroll
        for (int j = 0; j < 8; j++)
            #pragma unroll
            for (int q = 0; q < 4; q++) acc[i][j][q] = 0.f;

    PREFETCH(0, 0);

    for (int c = 0; c < CHK; c++) {
        if (c + 1 < CHK) {
            PREFETCH(c + 1, (c + 1) & 1);
            CPA_WAIT1();
        } else {
            CPA_WAIT0();
        }
        __syncthreads();
        const uint* S = smd + (c & 1) * 6144;
        const uint* Sal = S + 1536;
        const uint* Sbh = S + 3072;
        const uint* Sbl = S + 4608;

        uint bh[8][2], bl[8][2];
        #pragma unroll
        for (int nt = 0; nt < 8; nt++) {
            int n = wn * 64 + nt * 8 + g;
            bh[nt][0] = Sbh[n * 12 + t]; bh[nt][1] = Sbh[n * 12 + t + 4];
            bl[nt][0] = Sbl[n * 12 + t]; bl[nt][1] = Sbl[n * 12 + t + 4];
        }
        #pragma unroll
        for (int mt = 0; mt < 2; mt++) {
            int rb = wm * 32 + mt * 16;
            uint ah0 = S[(rb + g) * 12 + t],       ah1 = S[(rb + 8 + g) * 12 + t];
            uint ah2 = S[(rb + g) * 12 + t + 4],   ah3 = S[(rb + 8 + g) * 12 + t + 4];
            uint al0 = Sal[(rb + g) * 12 + t],     al1 = Sal[(rb + 8 + g) * 12 + t];
            uint al2 = Sal[(rb + g) * 12 + t + 4], al3 = Sal[(rb + 8 + g) * 12 + t + 4];
            #pragma unroll
            for (int nt = 0; nt < 8; nt++) {
                mma16816(acc[mt][nt], ah0, ah1, ah2, ah3, bh[nt][0], bh[nt][1]);
                mma16816(acc[mt][nt], ah0, ah1, ah2, ah3, bl[nt][0], bl[nt][1]);
                mma16816(acc[mt][nt], al0, al1, al2, al3, bh[nt][0], bh[nt][1]);
            }
        }
        __syncthreads();
    }
#undef PREFETCH

    if (OUTMODE == 3) {
        // ---- fused classifier head: park relu(m) tile in smem, compute out[row][0..9]
        float* Ms   = (float*)smd;             // [128][132] with wn-gap layout
        float* Wsm2 = ((float*)smd) + 16896;   // [128][10]
        float* bs2  = Wsm2 + 1280;             // [10]
        for (int i = tid; i < 1280; i += 256) Wsm2[i] = W2[i];
        if (tid < 10) bs2[tid] = B2[tid];
        #pragma unroll
        for (int nt = 0; nt < 8; nt++) {
            int mo = nt * 8 + 2 * t + wn * 66;
            int cc = wn * 64 + nt * 8 + 2 * t;
            float b0 = sbias[cc], b1 = sbias[cc + 1];
            #pragma unroll
            for (int mt = 0; mt < 2; mt++) {
                int rowl = wm * 32 + mt * 16 + g;
                float d0 = fmaxf(acc[mt][nt][0] + b0, 0.f);
                float d1 = fmaxf(acc[mt][nt][1] + b1, 0.f);
                float d2 = fmaxf(acc[mt][nt][2] + b0, 0.f);
                float d3 = fmaxf(acc[mt][nt][3] + b1, 0.f);
                *(float2*)&Ms[rowl * 132 + mo]       = make_float2(d0, d1);
                *(float2*)&Ms[(rowl + 8) * 132 + mo] = make_float2(d2, d3);
            }
        }
        __syncthreads();
        int row = tid >> 1, hf = tid & 1;
        float a10[10];
        #pragma unroll
        for (int c = 0; c < 10; c++) a10[c] = 0.f;
        const float* wb = Wsm2 + hf * 640;
        const float* mb = Ms + row * 132 + hf * 66;
        #pragma unroll 4
        for (int k = 0; k < 64; k++) {
            float mv = mb[k];
            const float* w = wb + k * 10;
            float2 w01 = *(const float2*)(w);
            float2 w23 = *(const float2*)(w + 2);
            float2 w45 = *(const float2*)(w + 4);
            float2 w67 = *(const float2*)(w + 6);
            float2 w89 = *(const float2*)(w + 8);
            a10[0] = fmaf(mv, w01.x, a10[0]); a10[1] = fmaf(mv, w01.y, a10[1]);
            a10[2] = fmaf(mv, w23.x, a10[2]); a10[3] = fmaf(mv, w23.y, a10[3]);
            a10[4] = fmaf(mv, w45.x, a10[4]); a10[5] = fmaf(mv, w45.y, a10[5]);
            a10[6] = fmaf(mv, w67.x, a10[6]); a10[7] = fmaf(mv, w67.y, a10[7]);
            a10[8] = fmaf(mv, w89.x, a10[8]); a10[9] = fmaf(mv, w89.y, a10[9]);
        }
        #pragma unroll
        for (int c = 0; c < 10; c++) a10[c] += __shfl_xor_sync(0xffffffffu, a10[c], 1);
        int gr = row0 + row;
        if (hf == 0 && gr < NN) {
            #pragma unroll
            for (int c = 0; c < 10; c++) OutF[(size_t)gr * 10 + c] = a10[c] + bs2[c];
        }
        return;
    }

    // ---- epilogue (modes 1/2): bias (+relu), pair stores, optional fused BN stats
    #pragma unroll
    for (int nt = 0; nt < 8; nt++) {
        int cc = wn * 64 + nt * 8 + 2 * t;
        float b0 = sbias[cc], b1 = sbias[cc + 1];
        float s0 = 0.f, q0 = 0.f, s1 = 0.f, q1 = 0.f;
        #pragma unroll
        for (int mt = 0; mt < 2; mt++) {
            int r0r = row0 + wm * 32 + mt * 16 + g;
            float d0 = acc[mt][nt][0] + b0, d1 = acc[mt][nt][1] + b1;
            float d2 = acc[mt][nt][2] + b0, d3 = acc[mt][nt][3] + b1;
            if (RELU) {
                d0 = fmaxf(d0, 0.f); d1 = fmaxf(d1, 0.f);
                d2 = fmaxf(d2, 0.f); d3 = fmaxf(d3, 0.f);
            }
            uint h, l;
            if (r0r < NN) {
                split2(d0, d1, h, l);
                Oh[(size_t)r0r * 64 + (cc >> 1)] = h;
                Ol[(size_t)r0r * 64 + (cc >> 1)] = l;
            }
            if (r0r + 8 < NN) {
                split2(d2, d3, h, l);
                Oh[(size_t)(r0r + 8) * 64 + (cc >> 1)] = h;
                Ol[(size_t)(r0r + 8) * 64 + (cc >> 1)] = l;
            }
            if (OUTMODE == 2) {
                if (r0r < NN) {
                    s0 += d0; q0 = fmaf(d0, d0, q0);
                    s1 += d1; q1 = fmaf(d1, d1, q1);
                }
                if (r0r + 8 < NN) {
                    s0 += d2; q0 = fmaf(d2, d2, q0);
                    s1 += d3; q1 = fmaf(d3, d3, q1);
                }
            }
        }
        if (OUTMODE == 2) {
            #pragma unroll
            for (int off = 4; off < 32; off <<= 1) {
                s0 += __shfl_xor_sync(0xffffffffu, s0, off);
                q0 += __shfl_xor_sync(0xffffffffu, q0, off);
                s1 += __shfl_xor_sync(0xffffffffu, s1, off);
                q1 += __shfl_xor_sync(0xffffffffu, q1, off);
            }
            if (lane < 4) {
                atomicAdd(&g_stats[cc], s0);
                atomicAdd(&g_stats[128 + cc], q0);
                atomicAdd(&g_stats[cc + 1], s1);
                atomicAdd(&g_stats[128 + cc + 1], q1);
            }
        }
    }
}

// ---------------- BN finalize (self-cleans the accumulators for next use) ----------------
__global__ void k_bnfin(const float* __restrict__ g, const float* __restrict__ b) {
    int c = threadIdx.x;
    float inv = 1.f / (float)NN;
    float mean = g_stats[c] * inv;
    float var = g_stats[128 + c] * inv - mean * mean;
    float rstd = rsqrtf(var + 1e-5f);
    float sc = g[c] * rstd;
    g_stats[256 + c] = sc;
    g_stats[384 + c] = b[c] - mean * sc;
    g_stats[c] = 0.f;
    g_stats[128 + c] = 0.f;
}

// bnapply2: pair in -> fp32 latent (d_out) + pair out (classifier input)
__global__ void k_bnapply2(const uint* __restrict__ Ih, const uint* __restrict__ Il,
                           float* __restrict__ OutF, uint* __restrict__ Oh,
                           uint* __restrict__ Ol) {
    int i = blockIdx.x * blockDim.x + threadIdx.x;
    if (i >= NN * 64) return;
    int c = (i & 63) * 2;
    float2 fh = bf2f(Ih[i]);
    float2 fl = bf2f(Il[i]);
    float v0 = fh.x + fl.x, v1 = fh.y + fl.y;
    float y0 = fmaxf(fmaf(v0, g_stats[256 + c], g_stats[384 + c]), 0.f);
    float y1 = fmaxf(fmaf(v1, g_stats[257 + c], g_stats[385 + c]), 0.f);
    int r = i >> 6;
    *(float2*)(OutF + (size_t)r * 128 + c) = make_float2(y0, y1);
    uint h, l;
    split2(y0, y1, h, l);
    Oh[i] = h;
    Ol[i] = l;
}

// ---------------- launch ----------------
extern "C" void kernel_launch(void* const* d_in, const int* in_sizes, int n_in,
                              void* d_out, int out_size) {
    const float* x    = (const float*)d_in[0];
    const int*   ei   = (const int*)d_in[1];
    const float* w1a = (const float*)d_in[2];  const float* b1a = (const float*)d_in[3];
    const float* w1b = (const float*)d_in[4];  const float* b1b = (const float*)d_in[5];
    const float* w2a = (const float*)d_in[6];  const float* b2a = (const float*)d_in[7];
    const float* w2b = (const float*)d_in[8];  const float* b2b = (const float*)d_in[9];
    const float* bn1g = (const float*)d_in[10]; const float* bn1b = (const float*)d_in[11];
    const float* bn2g = (const float*)d_in[12]; const float* bn2b = (const float*)d_in[13];
    const float* mw1 = (const float*)d_in[14]; const float* mb1 = (const float*)d_in[15];
    const float* mw2 = (const float*)d_in[16]; const float* mb2 = (const float*)d_in[17];
    float* out = (float*)d_out;

    uint *P0h, *P0l, *P1h, *P1l, *P2h, *P2l, *Wh, *Wl;
    cudaGetSymbolAddress((void**)&P0h, g_P0h); cudaGetSymbolAddress((void**)&P0l, g_P0l);
    cudaGetSymbolAddress((void**)&P1h, g_P1h); cudaGetSymbolAddress((void**)&P1l, g_P1l);
    cudaGetSymbolAddress((void**)&P2h, g_P2h); cudaGetSymbolAddress((void**)&P2l, g_P2l);
    cudaGetSymbolAddress((void**)&Wh, g_Wh);   cudaGetSymbolAddress((void**)&Wl, g_Wl);

    const int GB = (NN + 127) / 128;  // 782
    const int EB = (EE + 255) / 256;
    const int SMEM_G = 2 * 6144 * 4;                 // 49152 B (modes 1/2)
    const int SMEM_H = (16896 + 1280 + 16) * 4;      // 72768 B (mode 3: m-tile + W2 + b2)

    cudaFuncSetAttribute(k_mgemm<64, true, 1>,   cudaFuncAttributeMaxDynamicSharedMemorySize, SMEM_G);
    cudaFuncSetAttribute(k_mgemm<128, false, 2>, cudaFuncAttributeMaxDynamicSharedMemorySize, SMEM_G);
    cudaFuncSetAttribute(k_mgemm<128, true, 1>,  cudaFuncAttributeMaxDynamicSharedMemorySize, SMEM_G);
    cudaFuncSetAttribute(k_mgemm<128, true, 3>,  cudaFuncAttributeMaxDynamicSharedMemorySize, SMEM_H);

    // ---- setup + CSR build
    k_setup<<<(NN + 255) / 256, 256>>>(ei, w1a, w1b, w2a, w2b, mw1);
    k_deg<<<EB, 256>>>(ei);
    k_scan_all<<<NB, 1024>>>();
    k_fill<<<EB, 256>>>(ei);

    // ---- conv1
    k_gather1<<<(NN * 16 + 127) / 128, 128>>>(x, P0h, P0l);
    k_mgemm<64, true, 1><<<GB, 256, SMEM_G>>>(P0h, P0l, Wh, Wl, b1a, 0, P1h, P1l, 0, 0);
    k_mgemm<128, false, 2><<<GB, 256, SMEM_G>>>(P1h, P1l, Wh + 8192, Wl + 8192, b1b, 0, P2h, P2l, 0, 0);
    k_bnfin<<<1, 128>>>(bn1g, bn1b);
    // ---- conv2 (gather applies relu(bn(.)) per term)
    k_gather2<<<(NN + 3) / 4, 128>>>(P2h, P2l, P0h, P0l);
    k_mgemm<128, true, 1><<<GB, 256, SMEM_G>>>(P0h, P0l, Wh + 2 * 8192, Wl + 2 * 8192, b2a, 0, P1h, P1l, 0, 0);
    k_mgemm<128, false, 2><<<GB, 256, SMEM_G>>>(P1h, P1l, Wh + 3 * 8192, Wl + 3 * 8192, b2b, 0, P2h, P2l, 0, 0);
    k_bnfin<<<1, 128>>>(bn2g, bn2b);
    k_bnapply2<<<(NN * 64 + 255) / 256, 256>>>(P2h, P2l, out, P0h, P0l);
    // ---- classifier (fused head -> class_out)
    k_mgemm<128, true, 3><<<GB, 256, SMEM_H>>>(P0h, P0l, Wh + 4 * 8192, Wl + 4 * 8192, mb1,
                                               out + (size_t)NN * 128, 0, 0, mw2, mb2);
}

// round 12
// speedup vs baseline: 1.2342x; 1.1143x over previous
#include <cuda_runtime.h>
#include <cuda_bf16.h>

#define NN 100000
#define FF 64
#define HH 128
#define CC 10
#define EE 1600000
#define NB 98   // ceil(NN/1024)

typedef unsigned int uint;

// ---------------- scratch ----------------
__device__ uint g_P0h[(size_t)NN * 64], g_P0l[(size_t)NN * 64];
__device__ uint g_P2h[(size_t)NN * 64], g_P2l[(size_t)NN * 64];
__device__ uint g_Wh[5 * 8192], g_Wl[5 * 8192];
__device__ int g_deg[NN], g_rowptr[NN + 1], g_cur[NN], g_adj[EE];
__device__ int g_bsum[NB], g_bpre[NB];
__device__ float g_stats[512];   // [0:128) sum [128:256) sumsq [256:384) scale [384:512) shift
__device__ int g_is64;
__device__ int g_cnt, g_flag;

// ---------------- helpers ----------------
__device__ __forceinline__ uint pckbf(__nv_bfloat16 a, __nv_bfloat16 b) {
    __nv_bfloat162 t; t.x = a; t.y = b;
    return *reinterpret_cast<uint*>(&t);
}
__device__ __forceinline__ void split2(float x, float y, uint& h, uint& l) {
    __nv_bfloat16 hx = __float2bfloat16_rn(x), hy = __float2bfloat16_rn(y);
    float rx = x - __bfloat162float(hx), ry = y - __bfloat162float(hy);
    h = pckbf(hx, hy);
    l = pckbf(__float2bfloat16_rn(rx), __float2bfloat16_rn(ry));
}
__device__ __forceinline__ float2 bf2f(uint u) {
    __nv_bfloat162 b = *reinterpret_cast<__nv_bfloat162*>(&u);
    return make_float2(__bfloat162float(b.x), __bfloat162float(b.y));
}
__device__ __forceinline__ void mma16816(float* d, uint a0, uint a1, uint a2,
                                         uint a3, uint b0, uint b1) {
    asm volatile("mma.sync.aligned.m16n8k16.row.col.f32.bf16.bf16.f32 "
                 "{%0,%1,%2,%3},{%4,%5,%6,%7},{%8,%9},{%0,%1,%2,%3};"
                 : "+f"(d[0]), "+f"(d[1]), "+f"(d[2]), "+f"(d[3])
                 : "r"(a0), "r"(a1), "r"(a2), "r"(a3), "r"(b0), "r"(b1));
}
__device__ __forceinline__ void eidx(const int* ei, int e, int& s, int& d) {
    if (g_is64) { s = ei[2 * e]; d = ei[2 * EE + 2 * e]; }
    else        { s = ei[e];     d = ei[EE + e]; }
}
__device__ __forceinline__ uint smem_u32(const void* p) {
    uint a;
    asm("{ .reg .u64 t; cvta.to.shared.u64 t, %1; cvt.u32.u64 %0, t; }" : "=r"(a) : "l"(p));
    return a;
}
__device__ __forceinline__ void cpa16(uint dst, const void* src, int sz) {
    asm volatile("cp.async.cg.shared.global [%0], [%1], 16, %2;"
                 :: "r"(dst), "l"(src), "r"(sz));
}
#define CPA_COMMIT() asm volatile("cp.async.commit_group;" ::: "memory")
#define CPA_WAIT1()  asm volatile("cp.async.wait_group 1;" ::: "memory")
#define CPA_WAIT0()  asm volatile("cp.async.wait_group 0;" ::: "memory")

// ---------------- setup: zero deg + sync flags + dtype detect + weight pre-split ----------------
__global__ void k_setup(const int* __restrict__ ei,
                        const float* __restrict__ w1a, const float* __restrict__ w1b,
                        const float* __restrict__ w2a, const float* __restrict__ w2b,
                        const float* __restrict__ mw1) {
    int i = blockIdx.x * blockDim.x + threadIdx.x;
    if (i < NN) g_deg[i] = 0;
    if (i == 0) {
        int nz = 0;
        for (int k = 0; k < 1024; k++) nz |= ei[2 * k + 1];
        g_is64 = (nz == 0) ? 1 : 0;
        g_cnt = 0;
        g_flag = 0;
    }
    if (i < 4096 + 4 * 8192) {
        const float* W;
        int slot, li, RW;
        if (i < 4096) { W = w1a; slot = 0; li = i; RW = 32; }
        else {
            int j = i - 4096;
            int s = j >> 13;
            li = j & 8191;
            RW = 64;
            slot = 1 + s;
            W = (s == 0) ? w1b : (s == 1) ? w2a : (s == 2) ? w2b : mw1;
        }
        int n = li / RW, kp = li - n * RW;
        split2(W[(size_t)(2 * kp) * 128 + n], W[(size_t)(2 * kp + 1) * 128 + n],
               g_Wh[slot * 8192 + li], g_Wl[slot * 8192 + li]);
    }
}

// ---------------- CSR build ----------------
__global__ void k_deg(const int* __restrict__ ei) {
    int e = blockIdx.x * blockDim.x + threadIdx.x;
    if (e >= EE) return;
    int s, d;
    eidx(ei, e, s, d);
    if ((unsigned)s >= NN || (unsigned)d >= NN) return;
    atomicAdd(&g_deg[d], 1);
}

// single-kernel scan: per-chunk scan + global sync via counter/flag (all 98 blocks resident)
__global__ void __launch_bounds__(1024) k_scan_all() {
    __shared__ int sh[1024];
    __shared__ int s2[128];
    __shared__ int lastf;
    int t = threadIdx.x, b = blockIdx.x;
    int i = b * 1024 + t;
    int d = (i < NN) ? g_deg[i] : 0;
    sh[t] = d;
    __syncthreads();
    for (int off = 1; off < 1024; off <<= 1) {
        int v = (t >= off) ? sh[t - off] : 0;
        __syncthreads();
        sh[t] += v;
        __syncthreads();
    }
    if (t == 1023) {
        g_bsum[b] = sh[1023];
        __threadfence();
        lastf = (atomicAdd(&g_cnt, 1) == NB - 1);
    }
    __syncthreads();
    if (lastf) {
        if (t < 128) s2[t] = (t < NB) ? ((volatile int*)g_bsum)[t] : 0;
        __syncthreads();
        for (int off = 1; off < 128; off <<= 1) {
            int v = (t < 128 && t >= off) ? s2[t - off] : 0;
            __syncthreads();
            if (t < 128) s2[t] += v;
            __syncthreads();
        }
        if (t < NB) g_bpre[t] = (t == 0) ? 0 : s2[t - 1];
        if (t == NB - 1) g_rowptr[NN] = s2[t];
        __threadfence();
        __syncthreads();
        if (t == 0) atomicExch(&g_flag, 1);
    }
    if (t == 0) {
        while (atomicAdd(&g_flag, 0) == 0) { }
    }
    __syncthreads();
    if (i < NN) {
        int r = ((volatile int*)g_bpre)[b] + sh[t] - d;
        g_rowptr[i] = r;
        g_cur[i] = r;
    }
}

__global__ void k_fill(const int* __restrict__ ei) {
    int e = blockIdx.x * blockDim.x + threadIdx.x;
    if (e >= EE) return;
    int s, d;
    eidx(ei, e, s, d);
    if ((unsigned)s >= NN || (unsigned)d >= NN) return;
    int pos = atomicAdd(&g_cur[d], 1);
    g_adj[pos] = s;
}

// ---------------- gather1: agg = x_self + sum x_j, split to pair (width 64) ----------------
__global__ void k_gather1(const float* __restrict__ x, uint* __restrict__ Oh,
                          uint* __restrict__ Ol) {
    int gi = blockIdx.x * blockDim.x + threadIdx.x;
    int node = gi >> 4, l = gi & 15;
    if (node >= NN) return;
    const float4* xr = (const float4*)x;
    float4 acc = xr[(size_t)node * 16 + l];
    int p = g_rowptr[node], end = g_rowptr[node + 1];
    for (; p + 1 < end; p += 2) {
        int j0 = g_adj[p], j1 = g_adj[p + 1];
        float4 a = xr[(size_t)j0 * 16 + l];
        float4 b = xr[(size_t)j1 * 16 + l];
        acc.x += a.x + b.x; acc.y += a.y + b.y;
        acc.z += a.z + b.z; acc.w += a.w + b.w;
    }
    if (p < end) {
        float4 a = xr[(size_t)g_adj[p] * 16 + l];
        acc.x += a.x; acc.y += a.y; acc.z += a.z; acc.w += a.w;
    }
    uint h0, l0, h1, l1;
    split2(acc.x, acc.y, h0, l0);
    split2(acc.z, acc.w, h1, l1);
    size_t o = (size_t)node * 32 + l * 2;
    *(uint2*)(Oh + o) = make_uint2(h0, h1);
    *(uint2*)(Ol + o) = make_uint2(l0, l1);
}

// ---------------- gather2: agg = sum_{self+nbrs} relu(bn(v)), pair width 128 ----------------
__global__ void k_gather2(const uint* __restrict__ Ih, const uint* __restrict__ Il,
                          uint* __restrict__ Oh, uint* __restrict__ Ol) {
    int node = blockIdx.x * 4 + (threadIdx.x >> 5);
    int l = threadIdx.x & 31;
    if (node >= NN) return;
    float4 sc = *(const float4*)&g_stats[256 + l * 4];
    float4 sh = *(const float4*)&g_stats[384 + l * 4];
    float a0 = 0.f, a1 = 0.f, a2 = 0.f, a3 = 0.f;
#define ADDROW(j) do { \
        size_t _o = (size_t)(j) * 64 + l * 2; \
        uint2 uh = *(const uint2*)(Ih + _o); \
        uint2 ul = *(const uint2*)(Il + _o); \
        float2 fa = bf2f(uh.x), fb = bf2f(ul.x), fc = bf2f(uh.y), fd = bf2f(ul.y); \
        a0 += fmaxf(fmaf(fa.x + fb.x, sc.x, sh.x), 0.f); \
        a1 += fmaxf(fmaf(fa.y + fb.y, sc.y, sh.y), 0.f); \
        a2 += fmaxf(fmaf(fc.x + fd.x, sc.z, sh.z), 0.f); \
        a3 += fmaxf(fmaf(fc.y + fd.y, sc.w, sh.w), 0.f); \
    } while (0)
    ADDROW(node);
    int p = g_rowptr[node], end = g_rowptr[node + 1];
    for (; p + 1 < end; p += 2) {
        int j0 = g_adj[p], j1 = g_adj[p + 1];
        ADDROW(j0);
        ADDROW(j1);
    }
    if (p < end) ADDROW(g_adj[p]);
#undef ADDROW
    uint h0, l0, h1, l1;
    split2(a0, a1, h0, l0);
    split2(a2, a3, h1, l1);
    size_t o = (size_t)node * 64 + l * 2;
    *(uint2*)(Oh + o) = make_uint2(h0, h1);
    *(uint2*)(Ol + o) = make_uint2(l0, l1);
}

// ---------------- fused GIN-MLP: Out = (relu(A@W1+b1))@W2+b2, pair out + BN stats ----------------
// Phase 1: 2-stage cp.async GEMM (A global pair, W1) -> acc.
// Park relu(acc+b1) as split pair in smem Th/Tl [128][65] @word0 (overlays dead stage region).
// Phase 2: GEMM with A from parked smem, W2 double-buffered @word16640 (2x3072 words).
// Total smem: 22784 words = 91136 B -> 2 CTAs/SM.
template <int K1>
__global__ void __launch_bounds__(256, 2)
k_mlp(const uint* __restrict__ Ah, const uint* __restrict__ Al,
      const uint* __restrict__ W1h, const uint* __restrict__ W1l,
      const float* __restrict__ b1,
      const uint* __restrict__ W2h, const uint* __restrict__ W2l,
      const float* __restrict__ b2,
      uint* __restrict__ Oh, uint* __restrict__ Ol) {
    extern __shared__ uint smd[];
    __shared__ float sbias1[128];
    __shared__ float sbias2[128];

    const int tid = threadIdx.x;
    const int wid = tid >> 5, lane = tid & 31;
    const int wm = wid >> 1, wn = wid & 1;
    const int g = lane >> 2, t = lane & 3;
    const int row0 = blockIdx.x * 128;
    const int RW1 = K1 / 2;
    const int CHK1 = K1 / 16;

    const int r = tid >> 1, half = tid & 1;
    const uint sb = smem_u32(smd);
    const int rr = min(row0 + r, NN - 1);
    const int okA = (row0 + r < NN) ? 16 : 0;

    if (tid < 128) { sbias1[tid] = b1[tid]; sbias2[tid] = b2[tid]; }

#define PREFETCH(c, st) do { \
        uint _d = sb + (uint)((st) * 6144 + r * 12 + half * 4) * 4u; \
        size_t _ao = (size_t)rr * RW1 + (c) * 8 + half * 4; \
        size_t _wo = (size_t)r * RW1 + (c) * 8 + half * 4; \
        cpa16(_d,         Ah + _ao, okA); \
        cpa16(_d + 6144,  Al + _ao, okA); \
        cpa16(_d + 12288, W1h + _wo, 16); \
        cpa16(_d + 18432, W1l + _wo, 16); \
        CPA_COMMIT(); \
    } while (0)
#define PREFB(c, st) do { \
        uint _d = sb + (uint)(16640 + (st) * 3072 + r * 12 + half * 4) * 4u; \
        size_t _wo = (size_t)r * 64 + (c) * 8 + half * 4; \
        cpa16(_d,        W2h + _wo, 16); \
        cpa16(_d + 6144, W2l + _wo, 16); \
        CPA_COMMIT(); \
    } while (0)

    float acc[2][8][4];
    #pragma unroll
    for (int i = 0; i < 2; i++)
        #pragma unroll
        for (int j = 0; j < 8; j++)
            #pragma unroll
            for (int q = 0; q < 4; q++) acc[i][j][q] = 0.f;

    // ================= phase 1 =================
    PREFETCH(0, 0);
    for (int c = 0; c < CHK1; c++) {
        if (c + 1 < CHK1) {
            PREFETCH(c + 1, (c + 1) & 1);
            CPA_WAIT1();
        } else {
            CPA_WAIT0();
        }
        __syncthreads();
        const uint* S = smd + (c & 1) * 6144;
        const uint* Sal = S + 1536;
        const uint* Sbh = S + 3072;
        const uint* Sbl = S + 4608;

        uint bh[8][2], bl[8][2];
        #pragma unroll
        for (int nt = 0; nt < 8; nt++) {
            int n = wn * 64 + nt * 8 + g;
            bh[nt][0] = Sbh[n * 12 + t]; bh[nt][1] = Sbh[n * 12 + t + 4];
            bl[nt][0] = Sbl[n * 12 + t]; bl[nt][1] = Sbl[n * 12 + t + 4];
        }
        #pragma unroll
        for (int mt = 0; mt < 2; mt++) {
            int rb = wm * 32 + mt * 16;
            uint ah0 = S[(rb + g) * 12 + t],       ah1 = S[(rb + 8 + g) * 12 + t];
            uint ah2 = S[(rb + g) * 12 + t + 4],   ah3 = S[(rb + 8 + g) * 12 + t + 4];
            uint al0 = Sal[(rb + g) * 12 + t],     al1 = Sal[(rb + 8 + g) * 12 + t];
            uint al2 = Sal[(rb + g) * 12 + t + 4], al3 = Sal[(rb + 8 + g) * 12 + t + 4];
            #pragma unroll
            for (int nt = 0; nt < 8; nt++) {
                mma16816(acc[mt][nt], ah0, ah1, ah2, ah3, bh[nt][0], bh[nt][1]);
                mma16816(acc[mt][nt], ah0, ah1, ah2, ah3, bl[nt][0], bl[nt][1]);
                mma16816(acc[mt][nt], al0, al1, al2, al3, bh[nt][0], bh[nt][1]);
            }
        }
        __syncthreads();
    }

    // ---- park T1 = relu(acc + b1) as split pair; Th @0, Tl @8320, stride 65
    {
        uint* Th = smd;
        uint* Tl = smd + 8320;
        #pragma unroll
        for (int nt = 0; nt < 8; nt++) {
            int cc = wn * 64 + nt * 8 + 2 * t;
            int u = cc >> 1;
            float bb0 = sbias1[cc], bb1 = sbias1[cc + 1];
            #pragma unroll
            for (int mt = 0; mt < 2; mt++) {
                int rowl = wm * 32 + mt * 16 + g;
                float d0 = fmaxf(acc[mt][nt][0] + bb0, 0.f);
                float d1 = fmaxf(acc[mt][nt][1] + bb1, 0.f);
                float d2 = fmaxf(acc[mt][nt][2] + bb0, 0.f);
                float d3 = fmaxf(acc[mt][nt][3] + bb1, 0.f);
                uint h, l;
                split2(d0, d1, h, l);
                Th[rowl * 65 + u] = h; Tl[rowl * 65 + u] = l;
                split2(d2, d3, h, l);
                Th[(rowl + 8) * 65 + u] = h; Tl[(rowl + 8) * 65 + u] = l;
            }
        }
    }
    #pragma unroll
    for (int i = 0; i < 2; i++)
        #pragma unroll
        for (int j = 0; j < 8; j++)
            #pragma unroll
            for (int q = 0; q < 4; q++) acc[i][j][q] = 0.f;

    // ================= phase 2 (K=128, A from parked smem) =================
    PREFB(0, 0);
    for (int c = 0; c < 8; c++) {
        if (c + 1 < 8) {
            PREFB(c + 1, (c + 1) & 1);
            CPA_WAIT1();
        } else {
            CPA_WAIT0();
        }
        __syncthreads();
        const uint* Th = smd;
        const uint* Tl = smd + 8320;
        const uint* Sbh = smd + 16640 + (c & 1) * 3072;
        const uint* Sbl = Sbh + 1536;

        uint bh[8][2], bl[8][2];
        #pragma unroll
        for (int nt = 0; nt < 8; nt++) {
            int n = wn * 64 + nt * 8 + g;
            bh[nt][0] = Sbh[n * 12 + t]; bh[nt][1] = Sbh[n * 12 + t + 4];
            bl[nt][0] = Sbl[n * 12 + t]; bl[nt][1] = Sbl[n * 12 + t + 4];
        }
        #pragma unroll
        for (int mt = 0; mt < 2; mt++) {
            int rb = wm * 32 + mt * 16;
            uint ah0 = Th[(rb + g) * 65 + c * 8 + t],       ah1 = Th[(rb + 8 + g) * 65 + c * 8 + t];
            uint ah2 = Th[(rb + g) * 65 + c * 8 + t + 4],   ah3 = Th[(rb + 8 + g) * 65 + c * 8 + t + 4];
            uint al0 = Tl[(rb + g) * 65 + c * 8 + t],       al1 = Tl[(rb + 8 + g) * 65 + c * 8 + t];
            uint al2 = Tl[(rb + g) * 65 + c * 8 + t + 4],   al3 = Tl[(rb + 8 + g) * 65 + c * 8 + t + 4];
            #pragma unroll
            for (int nt = 0; nt < 8; nt++) {
                mma16816(acc[mt][nt], ah0, ah1, ah2, ah3, bh[nt][0], bh[nt][1]);
                mma16816(acc[mt][nt], ah0, ah1, ah2, ah3, bl[nt][0], bl[nt][1]);
                mma16816(acc[mt][nt], al0, al1, al2, al3, bh[nt][0], bh[nt][1]);
            }
        }
        __syncthreads();
    }
#undef PREFETCH
#undef PREFB

    // ---- epilogue: bias, pair store, fused BN column stats
    #pragma unroll
    for (int nt = 0; nt < 8; nt++) {
        int cc = wn * 64 + nt * 8 + 2 * t;
        float bb0 = sbias2[cc], bb1 = sbias2[cc + 1];
        float s0 = 0.f, q0 = 0.f, s1 = 0.f, q1 = 0.f;
        #pragma unroll
        for (int mt = 0; mt < 2; mt++) {
            int r0r = row0 + wm * 32 + mt * 16 + g;
            float d0 = acc[mt][nt][0] + bb0, d1 = acc[mt][nt][1] + bb1;
            float d2 = acc[mt][nt][2] + bb0, d3 = acc[mt][nt][3] + bb1;
            uint h, l;
            if (r0r < NN) {
                split2(d0, d1, h, l);
                Oh[(size_t)r0r * 64 + (cc >> 1)] = h;
                Ol[(size_t)r0r * 64 + (cc >> 1)] = l;
                s0 += d0; q0 = fmaf(d0, d0, q0);
                s1 += d1; q1 = fmaf(d1, d1, q1);
            }
            if (r0r + 8 < NN) {
                split2(d2, d3, h, l);
                Oh[(size_t)(r0r + 8) * 64 + (cc >> 1)] = h;
                Ol[(size_t)(r0r + 8) * 64 + (cc >> 1)] = l;
                s0 += d2; q0 = fmaf(d2, d2, q0);
                s1 += d3; q1 = fmaf(d3, d3, q1);
            }
        }
        #pragma unroll
        for (int off = 4; off < 32; off <<= 1) {
            s0 += __shfl_xor_sync(0xffffffffu, s0, off);
            q0 += __shfl_xor_sync(0xffffffffu, q0, off);
            s1 += __shfl_xor_sync(0xffffffffu, s1, off);
            q1 += __shfl_xor_sync(0xffffffffu, q1, off);
        }
        if (lane < 4) {
            atomicAdd(&g_stats[cc], s0);
            atomicAdd(&g_stats[128 + cc], q0);
            atomicAdd(&g_stats[cc + 1], s1);
            atomicAdd(&g_stats[128 + cc + 1], q1);
        }
    }
}

// ---------------- classifier GEMM with fused head (from R11, unchanged) ----------------
__global__ void __launch_bounds__(256, 2)
k_head(const uint* __restrict__ Ah, const uint* __restrict__ Al,
       const uint* __restrict__ Wh, const uint* __restrict__ Wl,
       const float* __restrict__ bias,
       float* __restrict__ OutF,
       const float* __restrict__ W2, const float* __restrict__ B2) {
    extern __shared__ uint smd[];
    __shared__ float sbias[128];

    const int tid = threadIdx.x;
    const int wid = tid >> 5, lane = tid & 31;
    const int wm = wid >> 1, wn = wid & 1;
    const int g = lane >> 2, t = lane & 3;
    const int row0 = blockIdx.x * 128;

    const int r = tid >> 1, half = tid & 1;
    const uint sb = smem_u32(smd);
    const int rr = min(row0 + r, NN - 1);
    const int okA = (row0 + r < NN) ? 16 : 0;

    if (tid < 128) sbias[tid] = bias[tid];

#define PREFETCH(c, st) do { \
        uint _d = sb + (uint)((st) * 6144 + r * 12 + half * 4) * 4u; \
        size_t _ao = (size_t)rr * 64 + (c) * 8 + half * 4; \
        size_t _wo = (size_t)r * 64 + (c) * 8 + half * 4; \
        cpa16(_d,         Ah + _ao, okA); \
        cpa16(_d + 6144,  Al + _ao, okA); \
        cpa16(_d + 12288, Wh + _wo, 16); \
        cpa16(_d + 18432, Wl + _wo, 16); \
        CPA_COMMIT(); \
    } while (0)

    float acc[2][8][4];
    #pragma unroll
    for (int i = 0; i < 2; i++)
        #pragma unroll
        for (int j = 0; j < 8; j++)
            #pragma unroll
            for (int q = 0; q < 4; q++) acc[i][j][q] = 0.f;

    PREFETCH(0, 0);
    for (int c = 0; c < 8; c++) {
        if (c + 1 < 8) {
            PREFETCH(c + 1, (c + 1) & 1);
            CPA_WAIT1();
        } else {
            CPA_WAIT0();
        }
        __syncthreads();
        const uint* S = smd + (c & 1) * 6144;
        const uint* Sal = S + 1536;
        const uint* Sbh = S + 3072;
        const uint* Sbl = S + 4608;

        uint bh[8][2], bl[8][2];
        #pragma unroll
        for (int nt = 0; nt < 8; nt++) {
            int n = wn * 64 + nt * 8 + g;
            bh[nt][0] = Sbh[n * 12 + t]; bh[nt][1] = Sbh[n * 12 + t + 4];
            bl[nt][0] = Sbl[n * 12 + t]; bl[nt][1] = Sbl[n * 12 + t + 4];
        }
        #pragma unroll
        for (int mt = 0; mt < 2; mt++) {
            int rb = wm * 32 + mt * 16;
            uint ah0 = S[(rb + g) * 12 + t],       ah1 = S[(rb + 8 + g) * 12 + t];
            uint ah2 = S[(rb + g) * 12 + t + 4],   ah3 = S[(rb + 8 + g) * 12 + t + 4];
            uint al0 = Sal[(rb + g) * 12 + t],     al1 = Sal[(rb + 8 + g) * 12 + t];
            uint al2 = Sal[(rb + g) * 12 + t + 4], al3 = Sal[(rb + 8 + g) * 12 + t + 4];
            #pragma unroll
            for (int nt = 0; nt < 8; nt++) {
                mma16816(acc[mt][nt], ah0, ah1, ah2, ah3, bh[nt][0], bh[nt][1]);
                mma16816(acc[mt][nt], ah0, ah1, ah2, ah3, bl[nt][0], bl[nt][1]);
                mma16816(acc[mt][nt], al0, al1, al2, al3, bh[nt][0], bh[nt][1]);
            }
        }
        __syncthreads();
    }
#undef PREFETCH

    // fused classifier head
    float* Ms   = (float*)smd;             // [128][132] with wn-gap layout
    float* Wsm2 = ((float*)smd) + 16896;   // [128][10]
    float* bs2  = Wsm2 + 1280;             // [10]
    for (int i = tid; i < 1280; i += 256) Wsm2[i] = W2[i];
    if (tid < 10) bs2[tid] = B2[tid];
    #pragma unroll
    for (int nt = 0; nt < 8; nt++) {
        int mo = nt * 8 + 2 * t + wn * 66;
        int cc = wn * 64 + nt * 8 + 2 * t;
        float b0 = sbias[cc], b1 = sbias[cc + 1];
        #pragma unroll
        for (int mt = 0; mt < 2; mt++) {
            int rowl = wm * 32 + mt * 16 + g;
            float d0 = fmaxf(acc[mt][nt][0] + b0, 0.f);
            float d1 = fmaxf(acc[mt][nt][1] + b1, 0.f);
            float d2 = fmaxf(acc[mt][nt][2] + b0, 0.f);
            float d3 = fmaxf(acc[mt][nt][3] + b1, 0.f);
            *(float2*)&Ms[rowl * 132 + mo]       = make_float2(d0, d1);
            *(float2*)&Ms[(rowl + 8) * 132 + mo] = make_float2(d2, d3);
        }
    }
    __syncthreads();
    int row = tid >> 1, hf = tid & 1;
    float a10[10];
    #pragma unroll
    for (int c = 0; c < 10; c++) a10[c] = 0.f;
    const float* wb = Wsm2 + hf * 640;
    const float* mb = Ms + row * 132 + hf * 66;
    #pragma unroll 4
    for (int k = 0; k < 64; k++) {
        float mv = mb[k];
        const float* w = wb + k * 10;
        float2 w01 = *(const float2*)(w);
        float2 w23 = *(const float2*)(w + 2);
        float2 w45 = *(const float2*)(w + 4);
        float2 w67 = *(const float2*)(w + 6);
        float2 w89 = *(const float2*)(w + 8);
        a10[0] = fmaf(mv, w01.x, a10[0]); a10[1] = fmaf(mv, w01.y, a10[1]);
        a10[2] = fmaf(mv, w23.x, a10[2]); a10[3] = fmaf(mv, w23.y, a10[3]);
        a10[4] = fmaf(mv, w45.x, a10[4]); a10[5] = fmaf(mv, w45.y, a10[5]);
        a10[6] = fmaf(mv, w67.x, a10[6]); a10[7] = fmaf(mv, w67.y, a10[7]);
        a10[8] = fmaf(mv, w89.x, a10[8]); a10[9] = fmaf(mv, w89.y, a10[9]);
    }
    #pragma unroll
    for (int c = 0; c < 10; c++) a10[c] += __shfl_xor_sync(0xffffffffu, a10[c], 1);
    int gr = row0 + row;
    if (hf == 0 && gr < NN) {
        #pragma unroll
        for (int c = 0; c < 10; c++) OutF[(size_t)gr * 10 + c] = a10[c] + bs2[c];
    }
}

// ---------------- BN finalize (self-cleans the accumulators for next use) ----------------
__global__ void k_bnfin(const float* __restrict__ g, const float* __restrict__ b) {
    int c = threadIdx.x;
    float inv = 1.f / (float)NN;
    float mean = g_stats[c] * inv;
    float var = g_stats[128 + c] * inv - mean * mean;
    float rstd = rsqrtf(var + 1e-5f);
    float sc = g[c] * rstd;
    g_stats[256 + c] = sc;
    g_stats[384 + c] = b[c] - mean * sc;
    g_stats[c] = 0.f;
    g_stats[128 + c] = 0.f;
}

// bnapply2: pair in -> fp32 latent (d_out) + pair out (classifier input)
__global__ void k_bnapply2(const uint* __restrict__ Ih, const uint* __restrict__ Il,
                           float* __restrict__ OutF, uint* __restrict__ Oh,
                           uint* __restrict__ Ol) {
    int i = blockIdx.x * blockDim.x + threadIdx.x;
    if (i >= NN * 64) return;
    int c = (i & 63) * 2;
    float2 fh = bf2f(Ih[i]);
    float2 fl = bf2f(Il[i]);
    float v0 = fh.x + fl.x, v1 = fh.y + fl.y;
    float y0 = fmaxf(fmaf(v0, g_stats[256 + c], g_stats[384 + c]), 0.f);
    float y1 = fmaxf(fmaf(v1, g_stats[257 + c], g_stats[385 + c]), 0.f);
    int r = i >> 6;
    *(float2*)(OutF + (size_t)r * 128 + c) = make_float2(y0, y1);
    uint h, l;
    split2(y0, y1, h, l);
    Oh[i] = h;
    Ol[i] = l;
}

// ---------------- launch ----------------
extern "C" void kernel_launch(void* const* d_in, const int* in_sizes, int n_in,
                              void* d_out, int out_size) {
    const float* x    = (const float*)d_in[0];
    const int*   ei   = (const int*)d_in[1];
    const float* w1a = (const float*)d_in[2];  const float* b1a = (const float*)d_in[3];
    const float* w1b = (const float*)d_in[4];  const float* b1b = (const float*)d_in[5];
    const float* w2a = (const float*)d_in[6];  const float* b2a = (const float*)d_in[7];
    const float* w2b = (const float*)d_in[8];  const float* b2b = (const float*)d_in[9];
    const float* bn1g = (const float*)d_in[10]; const float* bn1b = (const float*)d_in[11];
    const float* bn2g = (const float*)d_in[12]; const float* bn2b = (const float*)d_in[13];
    const float* mw1 = (const float*)d_in[14]; const float* mb1 = (const float*)d_in[15];
    const float* mw2 = (const float*)d_in[16]; const float* mb2 = (const float*)d_in[17];
    float* out = (float*)d_out;

    uint *P0h, *P0l, *P2h, *P2l, *Wh, *Wl;
    cudaGetSymbolAddress((void**)&P0h, g_P0h); cudaGetSymbolAddress((void**)&P0l, g_P0l);
    cudaGetSymbolAddress((void**)&P2h, g_P2h); cudaGetSymbolAddress((void**)&P2l, g_P2l);
    cudaGetSymbolAddress((void**)&Wh, g_Wh);   cudaGetSymbolAddress((void**)&Wl, g_Wl);

    const int GB = (NN + 127) / 128;  // 782
    const int EB = (EE + 255) / 256;
    const int SMEM_F = 22784 * 4;                 // 91136 B (fused MLP)
    const int SMEM_H = (16896 + 1280 + 16) * 4;   // 72768 B (head)

    cudaFuncSetAttribute(k_mlp<64>,  cudaFuncAttributeMaxDynamicSharedMemorySize, SMEM_F);
    cudaFuncSetAttribute(k_mlp<128>, cudaFuncAttributeMaxDynamicSharedMemorySize, SMEM_F);
    cudaFuncSetAttribute(k_head,     cudaFuncAttributeMaxDynamicSharedMemorySize, SMEM_H);

    // ---- setup + CSR build
    k_setup<<<(NN + 255) / 256, 256>>>(ei, w1a, w1b, w2a, w2b, mw1);
    k_deg<<<EB, 256>>>(ei);
    k_scan_all<<<NB, 1024>>>();
    k_fill<<<EB, 256>>>(ei);

    // ---- conv1 (fused MLP)
    k_gather1<<<(NN * 16 + 127) / 128, 128>>>(x, P0h, P0l);
    k_mlp<64><<<GB, 256, SMEM_F>>>(P0h, P0l, Wh, Wl, b1a,
                                   Wh + 8192, Wl + 8192, b1b, P2h, P2l);
    k_bnfin<<<1, 128>>>(bn1g, bn1b);
    // ---- conv2 (gather applies relu(bn(.)) per term; fused MLP)
    k_gather2<<<(NN + 3) / 4, 128>>>(P2h, P2l, P0h, P0l);
    k_mlp<128><<<GB, 256, SMEM_F>>>(P0h, P0l, Wh + 2 * 8192, Wl + 2 * 8192, b2a,
                                    Wh + 3 * 8192, Wl + 3 * 8192, b2b, P2h, P2l);
    k_bnfin<<<1, 128>>>(bn2g, bn2b);
    k_bnapply2<<<(NN * 64 + 255) / 256, 256>>>(P2h, P2l, out, P0h, P0l);
    // ---- classifier (fused head -> class_out)
    k_head<<<GB, 256, SMEM_H>>>(P0h, P0l, Wh + 4 * 8192, Wl + 4 * 8192, mb1,
                                out + (size_t)NN * 128, mw2, mb2);
}